// round 6
// baseline (speedup 1.0000x reference)
#include <cuda_runtime.h>
#include <cuda_bf16.h>
#include <math.h>
#include <stdint.h>

// ---------------------------------------------------------------------------
// Problem constants
// ---------------------------------------------------------------------------
#define NN    50000
#define EE    800000
#define EMB   256
#define HID   512
#define DDISC 64
#define DCONT 13
#define CAT   (4*EMB)      // 1024
#define SLOPE 0.01f

// ---------------------------------------------------------------------------
// Scratch — __device__ globals (no cudaMalloc allowed)
// ---------------------------------------------------------------------------
__device__ float g_Y [(long)NN*EMB];     // conv pre-aggregation (fp32)
__device__ float g_S [(long)NN*EMB];     // s
__device__ float g_sci[NN];
__device__ float g_dinv[NN];
__device__ int   g_cnt[NN];
__device__ int   g_rowptr[NN+1];
__device__ int   g_cursor[NN];
__device__ int   g_colsrc[EE];
__device__ int   g_is64;

// bf16 split buffers (hi/lo)
__device__ __align__(16) __nv_bfloat16 g_Ah[(long)NN*CAT];   // concat split
__device__ __align__(16) __nv_bfloat16 g_Al[(long)NN*CAT];
__device__ __align__(16) __nv_bfloat16 g_Gh[(long)NN*EMB];   // gcn activation split
__device__ __align__(16) __nv_bfloat16 g_Gl[(long)NN*EMB];
__device__ __align__(16) __nv_bfloat16 g_Hh[(long)NN*HID];   // h_ci split
__device__ __align__(16) __nv_bfloat16 g_Hl[(long)NN*HID];
__device__ __align__(16) __nv_bfloat16 g_Dh[(long)NN*DDISC]; // discrete_x split
__device__ __align__(16) __nv_bfloat16 g_Dl[(long)NN*DDISC];
__device__ __align__(16) __nv_bfloat16 g_Wth[(long)CAT*HID]; // transposed weight split
__device__ __align__(16) __nv_bfloat16 g_Wtl[(long)CAT*HID];

// ---------------------------------------------------------------------------
// asm helpers (base ISA only — must compile for compute_103)
// ---------------------------------------------------------------------------
__device__ __forceinline__ uint32_t smem_u32(const void* p) {
    uint32_t a;
    asm("{ .reg .u64 t; cvta.to.shared.u64 t, %1; cvt.u32.u64 %0, t; }" : "=r"(a) : "l"(p));
    return a;
}
__device__ __forceinline__ void ldsm4(uint32_t& r0, uint32_t& r1, uint32_t& r2, uint32_t& r3,
                                      uint32_t addr) {
    asm volatile("ldmatrix.sync.aligned.m8n8.x4.shared.b16 {%0,%1,%2,%3}, [%4];"
                 : "=r"(r0), "=r"(r1), "=r"(r2), "=r"(r3) : "r"(addr));
}
__device__ __forceinline__ void mma16816(float* c, const uint32_t* a, const uint32_t* b) {
    asm volatile(
        "mma.sync.aligned.m16n8k16.row.col.f32.bf16.bf16.f32 "
        "{%0,%1,%2,%3}, {%4,%5,%6,%7}, {%8,%9}, {%0,%1,%2,%3};"
        : "+f"(c[0]), "+f"(c[1]), "+f"(c[2]), "+f"(c[3])
        : "r"(a[0]), "r"(a[1]), "r"(a[2]), "r"(a[3]), "r"(b[0]), "r"(b[1]));
}
__device__ __forceinline__ void cp16(uint32_t dst, const void* src, int sz) {
    asm volatile("cp.async.cg.shared.global [%0], [%1], 16, %2;"
                 :: "r"(dst), "l"(src), "r"(sz) : "memory");
}
__device__ __forceinline__ void cp_commit() {
    asm volatile("cp.async.commit_group;" ::: "memory");
}
__device__ __forceinline__ void cp_wait1() {
    asm volatile("cp.async.wait_group 1;" ::: "memory");
}
__device__ __forceinline__ void cp_wait0() {
    asm volatile("cp.async.wait_group 0;" ::: "memory");
}
// byte offset inside a [rows][32 halfs] tile (row stride 64B, 16B-chunk swizzle)
__device__ __forceinline__ uint32_t swa(int r, int ci) {
    return (uint32_t)(r * 64 + ((ci ^ (r & 3) ^ ((r >> 2) & 1)) * 16));
}
__device__ __forceinline__ void split_store(__nv_bfloat16* H, __nv_bfloat16* L,
                                            size_t off, float v0, float v1) {
    __nv_bfloat16 h0 = __float2bfloat16(v0);
    __nv_bfloat16 h1 = __float2bfloat16(v1);
    __nv_bfloat16 l0 = __float2bfloat16(v0 - __bfloat162float(h0));
    __nv_bfloat16 l1 = __float2bfloat16(v1 - __bfloat162float(h1));
    *(__nv_bfloat162*)(H + off) = __nv_bfloat162(h0, h1);
    *(__nv_bfloat162*)(L + off) = __nv_bfloat162(l0, l1);
}

// ---------------------------------------------------------------------------
// bf16x3 HMMA GEMM, cp.async 3-stage pipelined, one sync per K-chunk.
// C = act(A @ W + bias). A split [M,K] row-major; W split transposed [N,K].
// CTA tile 128x128, 8 warps (warp tile 32x64), K-chunk 32, K%32==0, N%128==0.
// MODE 0: write Cf fp32.  MODE 1: write split (Ch,Cl).
// MODE 2: write split + fp32 into Cf AND Cf2 (dual copy for output tuple).
// Dynamic smem: 3 stages x 32KB = 96KB.
// ---------------------------------------------------------------------------
#define STG 32768
template<int ACT, int MODE>
__global__ __launch_bounds__(256, 2)
void mma_gemm_kernel(const __nv_bfloat16* __restrict__ Ah,
                     const __nv_bfloat16* __restrict__ Al,
                     const __nv_bfloat16* __restrict__ Bh,   // [N,K]
                     const __nv_bfloat16* __restrict__ Bl,
                     const float* __restrict__ bias,
                     float* __restrict__ Cf, float* __restrict__ Cf2, int ldf,
                     __nv_bfloat16* __restrict__ Ch, __nv_bfloat16* __restrict__ Cl, int lds,
                     int M, int K, int N)
{
    extern __shared__ char sm[];
    const uint32_t sb = smem_u32(sm);
    const uint32_t oAH = 0, oAL = 8192, oBH = 16384, oBL = 24576;

    int tid = threadIdx.x;
    int wid = tid >> 5;
    int lane = tid & 31;
    int wm = wid & 3;
    int wn = wid >> 2;
    int row0 = blockIdx.y * 128;
    int col0 = blockIdx.x * 128;

    float acc[2][8][4];
    #pragma unroll
    for (int i = 0; i < 2; i++)
        #pragma unroll
        for (int j = 0; j < 8; j++)
            #pragma unroll
            for (int q = 0; q < 4; q++) acc[i][j][q] = 0.f;

    int Lg = lane >> 3;
    int Lr = lane & 7;
    const int nchunks = K >> 5;

    // ---- cp.async prefetch of one K-chunk into a stage buffer ----
    auto prefetch = [&](int ch, int stage) {
        int k0 = ch << 5;
        uint32_t base = sb + stage * STG;
        #pragma unroll
        for (int it = 0; it < 2; it++) {
            int idx = tid + it * 256;          // 0..511
            int r = idx >> 2, ci = idx & 3;
            uint32_t sw = swa(r, ci);
            int gr = row0 + r;
            int ok = (gr < M) ? 16 : 0;
            size_t ga = (size_t)(ok ? gr : 0) * K + k0 + ci * 8;
            cp16(base + oAH + sw, Ah + ga, ok);
            cp16(base + oAL + sw, Al + ga, ok);
            size_t gb = (size_t)(col0 + r) * K + k0 + ci * 8;
            cp16(base + oBH + sw, Bh + gb, 16);
            cp16(base + oBL + sw, Bl + gb, 16);
        }
        cp_commit();
    };

    // prologue: chunks 0 and 1 in flight
    prefetch(0, 0);
    if (nchunks > 1) prefetch(1, 1);

    for (int ch = 0; ch < nchunks; ch++) {
        // wait for chunk ch (allow the one newer group to stay in flight)
        if (ch < nchunks - 1) cp_wait1(); else cp_wait0();
        __syncthreads();
        uint32_t base = sb + (ch % 3) * STG;

        #pragma unroll
        for (int ks = 0; ks < 2; ks++) {
            uint32_t ah[2][4], al[2][4];
            #pragma unroll
            for (int ma = 0; ma < 2; ma++) {
                int ar = wm * 32 + ma * 16 + Lr + (Lg & 1) * 8;
                int ac = ks * 2 + (Lg >> 1);
                uint32_t sw = swa(ar, ac);
                ldsm4(ah[ma][0], ah[ma][1], ah[ma][2], ah[ma][3], base + oAH + sw);
                ldsm4(al[ma][0], al[ma][1], al[ma][2], al[ma][3], base + oAL + sw);
            }
            #pragma unroll
            for (int g = 0; g < 4; g++) {
                int br = wn * 64 + g * 16 + Lr + (Lg >> 1) * 8;
                int bc = ks * 2 + (Lg & 1);
                uint32_t sw = swa(br, bc);
                uint32_t bh[4], bl[4];
                ldsm4(bh[0], bh[1], bh[2], bh[3], base + oBH + sw);
                ldsm4(bl[0], bl[1], bl[2], bl[3], base + oBL + sw);
                #pragma unroll
                for (int ma = 0; ma < 2; ma++) {
                    mma16816(acc[ma][g*2+0], ah[ma], bh + 0);
                    mma16816(acc[ma][g*2+1], ah[ma], bh + 2);
                    mma16816(acc[ma][g*2+0], ah[ma], bl + 0);
                    mma16816(acc[ma][g*2+1], ah[ma], bl + 2);
                    mma16816(acc[ma][g*2+0], al[ma], bh + 0);
                    mma16816(acc[ma][g*2+1], al[ma], bh + 2);
                }
            }
        }
        // prefetch chunk ch+2 into stage (ch+2)%3 — safe: that stage held
        // chunk ch-1, whose consumers all passed this iteration's barrier.
        if (ch + 2 < nchunks) prefetch(ch + 2, (ch + 2) % 3);
    }

    // ---- epilogue ----
    int rbase = row0 + wm * 32 + (lane >> 2);
    int cbase = col0 + wn * 64 + (lane & 3) * 2;
    #pragma unroll
    for (int ma = 0; ma < 2; ma++) {
        #pragma unroll
        for (int na = 0; na < 8; na++) {
            int gc = cbase + na * 8;
            float b0 = bias ? bias[gc] : 0.f;
            float b1 = bias ? bias[gc + 1] : 0.f;
            #pragma unroll
            for (int h = 0; h < 2; h++) {
                int gr = rbase + ma * 16 + h * 8;
                if (gr < M) {
                    float v0 = acc[ma][na][h * 2 + 0] + b0;
                    float v1 = acc[ma][na][h * 2 + 1] + b1;
                    if (ACT == 1) {
                        v0 = v0 > 0.f ? v0 : SLOPE * v0;
                        v1 = v1 > 0.f ? v1 : SLOPE * v1;
                    }
                    if (MODE == 0 || MODE == 2) {
                        *(float2*)(Cf + (size_t)gr * ldf + gc) = make_float2(v0, v1);
                        if (MODE == 2)
                            *(float2*)(Cf2 + (size_t)gr * ldf + gc) = make_float2(v0, v1);
                    }
                    if (MODE == 1 || MODE == 2)
                        split_store(Ch, Cl, (size_t)gr * lds + gc, v0, v1);
                }
            }
        }
    }
}

// ---------------------------------------------------------------------------
// fp32 -> bf16 hi/lo split (input features; and transposed variant for weights)
// ---------------------------------------------------------------------------
__global__ void splitA_kernel(const float* __restrict__ X,
                              __nv_bfloat16* __restrict__ H,
                              __nv_bfloat16* __restrict__ L, long n)
{
    long i = (long)blockIdx.x * blockDim.x + threadIdx.x;
    if (i >= n) return;
    float a = X[i];
    __nv_bfloat16 h = __float2bfloat16(a);
    H[i] = h;
    L[i] = __float2bfloat16(a - __bfloat162float(h));
}

__global__ void splitWT_kernel(const float* __restrict__ W,   // [K,N]
                               __nv_bfloat16* __restrict__ H, // [N,K]
                               __nv_bfloat16* __restrict__ L,
                               int K, int N)
{
    long i = (long)blockIdx.x * blockDim.x + threadIdx.x;
    if (i >= (long)K * N) return;
    int k = (int)(i / N), nn = (int)(i % N);
    float a = W[i];
    __nv_bfloat16 h = __float2bfloat16(a);
    long o = (long)nn * K + k;
    H[o] = h;
    L[o] = __float2bfloat16(a - __bfloat162float(h));
}

// ---------------------------------------------------------------------------
// Edge dtype probe + graph preprocessing
// ---------------------------------------------------------------------------
__global__ void probe_kernel(const int* __restrict__ ei32, int nwords)
{
    __shared__ int nz;
    if (threadIdx.x == 0) nz = 0;
    __syncthreads();
    int lim = nwords < 4096 ? nwords : 4096;
    for (int i = 1 + 2 * threadIdx.x; i < lim; i += 2 * blockDim.x)
        if (ei32[i] != 0) atomicAdd(&nz, 1);
    __syncthreads();
    if (threadIdx.x == 0) g_is64 = (nz == 0) ? 1 : 0;
}

__device__ __forceinline__ int edge_at(const void* base, long i, int is64)
{
    return is64 ? (int)((const long long*)base)[i] : ((const int*)base)[i];
}

__global__ void zero_cnt_kernel(int n) {
    int i = blockIdx.x * blockDim.x + threadIdx.x;
    if (i < n) g_cnt[i] = 0;
}

__global__ void count_kernel(const void* __restrict__ ei, int e, int n) {
    int i = blockIdx.x * blockDim.x + threadIdx.x;
    if (i >= e) return;
    int is64 = g_is64;
    int d = edge_at(ei, (long)e + i, is64);
    if ((unsigned)d < (unsigned)n) atomicAdd(&g_cnt[d], 1);
}

__global__ void dinv_kernel(int n) {
    int i = blockIdx.x * blockDim.x + threadIdx.x;
    if (i < n) g_dinv[i] = rsqrtf((float)(g_cnt[i] + 1));
}

// fast single-block scan: serial per-thread segments + one 1024-wide scan
__global__ void scan_kernel(int n) {
    __shared__ int part[1024];
    int tid = threadIdx.x;
    int per = (n + 1023) >> 10;
    int beg = tid * per;
    int end = beg + per < n ? beg + per : n;
    int s = 0;
    for (int i = beg; i < end; i++) s += g_cnt[i];
    part[tid] = s;
    __syncthreads();
    for (int off = 1; off < 1024; off <<= 1) {
        int t = (tid >= off) ? part[tid - off] : 0;
        __syncthreads();
        part[tid] += t;
        __syncthreads();
    }
    int run = part[tid] - s;
    for (int i = beg; i < end; i++) {
        int v = g_cnt[i];
        g_rowptr[i] = run;
        g_cursor[i] = run;
        run += v;
    }
    if (tid == 1023) g_rowptr[n] = run;
}

__global__ void fill_kernel(const void* __restrict__ ei, int e, int n) {
    int i = blockIdx.x * blockDim.x + threadIdx.x;
    if (i >= e) return;
    int is64 = g_is64;
    int s = edge_at(ei, i, is64);
    int d = edge_at(ei, (long)e + i, is64);
    if ((unsigned)d < (unsigned)n && (unsigned)s < (unsigned)n) {
        int pos = atomicAdd(&g_cursor[d], 1);
        if (pos < EE) g_colsrc[pos] = s;
    }
}

// ---------------------------------------------------------------------------
// SIMT SGEMM for small-K continuous embeds (K=13), writes bf16 split directly.
// ---------------------------------------------------------------------------
__global__ __launch_bounds__(256)
void sgemm_split_kernel(const float* __restrict__ A, int lda,
                        const float* __restrict__ W,
                        const float* __restrict__ bias,
                        __nv_bfloat16* __restrict__ Ch,
                        __nv_bfloat16* __restrict__ Cl, int ldc,
                        int M, int K, int NC)
{
    const int BM = 128, BN = 128, BK = 8;
    __shared__ float As[BK][BM];
    __shared__ float Ws[BK][BN];

    int tid = threadIdx.x;
    int tx = tid & 15;
    int ty = tid >> 4;
    int row0 = blockIdx.y * BM;
    int col0 = blockIdx.x * BN;

    float acc[8][8];
    #pragma unroll
    for (int i = 0; i < 8; i++)
        #pragma unroll
        for (int j = 0; j < 8; j++) acc[i][j] = 0.f;

    int a_row = tid >> 1;
    int a_col = (tid & 1) * 4;
    int w_k = tid >> 5;
    int w_n = (tid & 31) * 4;

    for (int k0 = 0; k0 < K; k0 += BK) {
        #pragma unroll
        for (int j = 0; j < 4; j++) {
            int r = row0 + a_row, c = k0 + a_col + j;
            As[a_col + j][a_row] = (r < M && c < K) ? A[(long)r * lda + c] : 0.f;
        }
        #pragma unroll
        for (int j = 0; j < 4; j++) {
            int kk = k0 + w_k, nn = col0 + w_n + j;
            Ws[w_k][w_n + j] = (kk < K && nn < NC) ? W[(long)kk * NC + nn] : 0.f;
        }
        __syncthreads();
        #pragma unroll
        for (int k = 0; k < BK; k++) {
            float a[8], b[8];
            #pragma unroll
            for (int i = 0; i < 8; i++) a[i] = As[k][ty * 8 + i];
            #pragma unroll
            for (int j = 0; j < 8; j++) b[j] = Ws[k][tx * 8 + j];
            #pragma unroll
            for (int i = 0; i < 8; i++)
                #pragma unroll
                for (int j = 0; j < 8; j++)
                    acc[i][j] += a[i] * b[j];
        }
        __syncthreads();
    }

    #pragma unroll
    for (int i = 0; i < 8; i++) {
        int r = row0 + ty * 8 + i;
        if (r >= M) continue;
        #pragma unroll
        for (int j = 0; j < 8; j += 2) {
            int c = col0 + tx * 8 + j;
            if (c + 1 >= NC) continue;
            float v0 = acc[i][j] + bias[c];
            float v1 = acc[i][j + 1] + bias[c + 1];
            v0 = v0 > 0.f ? v0 : SLOPE * v0;
            v1 = v1 > 0.f ? v1 : SLOPE * v1;
            split_store(Ch, Cl, (size_t)r * ldc + c, v0, v1);
        }
    }
}

// ---------------------------------------------------------------------------
// GCN aggregation (one warp per node), float4 gathers, writes bf16 split.
// lane owns columns [lane*8, lane*8+8).
// ---------------------------------------------------------------------------
__global__ __launch_bounds__(256)
void agg_kernel(const float* __restrict__ Y, const float* __restrict__ bias,
                __nv_bfloat16* __restrict__ Oh, __nv_bfloat16* __restrict__ Ol,
                int ldc, int n)
{
    int warp = (blockIdx.x * blockDim.x + threadIdx.x) >> 5;
    int lane = threadIdx.x & 31;
    if (warp >= n) return;
    int beg = g_rowptr[warp], end = g_rowptr[warp + 1];
    int c0 = lane * 8;
    float4 a0 = make_float4(0.f, 0.f, 0.f, 0.f);
    float4 a1 = make_float4(0.f, 0.f, 0.f, 0.f);
    for (int e = beg; e < end; e++) {
        int s = g_colsrc[e];
        float w = g_dinv[s];
        const float4* yr = (const float4*)(Y + (size_t)s * EMB + c0);
        float4 y0 = yr[0], y1 = yr[1];
        a0.x += y0.x * w; a0.y += y0.y * w; a0.z += y0.z * w; a0.w += y0.w * w;
        a1.x += y1.x * w; a1.y += y1.y * w; a1.z += y1.z * w; a1.w += y1.w * w;
    }
    float di = g_dinv[warp];
    float dii = di * di;
    const float4* ys = (const float4*)(Y + (size_t)warp * EMB + c0);
    float4 s0 = ys[0], s1 = ys[1];
    const float4* bp = (const float4*)(bias + c0);
    float4 b0 = bp[0], b1 = bp[1];
    float v[8];
    v[0] = di * a0.x + dii * s0.x + b0.x;
    v[1] = di * a0.y + dii * s0.y + b0.y;
    v[2] = di * a0.z + dii * s0.z + b0.z;
    v[3] = di * a0.w + dii * s0.w + b0.w;
    v[4] = di * a1.x + dii * s1.x + b1.x;
    v[5] = di * a1.y + dii * s1.y + b1.y;
    v[6] = di * a1.z + dii * s1.z + b1.z;
    v[7] = di * a1.w + dii * s1.w + b1.w;
    size_t ob = (size_t)warp * ldc + c0;
    #pragma unroll
    for (int j = 0; j < 8; j += 2) {
        float v0 = v[j] > 0.f ? v[j] : SLOPE * v[j];
        float v1 = v[j+1] > 0.f ? v[j+1] : SLOPE * v[j+1];
        split_store(Oh, Ol, ob + j, v0, v1);
    }
}

// ---------------------------------------------------------------------------
// Final sigmoid head + small s_ci writeout
// ---------------------------------------------------------------------------
__global__ __launch_bounds__(256)
void final_kernel(const float* __restrict__ Wl2, const float* __restrict__ bl2, int n)
{
    int warp = (blockIdx.x * blockDim.x + threadIdx.x) >> 5;
    int lane = threadIdx.x & 31;
    if (warp >= n) return;
    const float* sr = g_S + (long)warp * EMB;
    float a = 0.f;
    #pragma unroll
    for (int j = 0; j < 8; j++) {
        int c = lane + 32 * j;
        a += sr[c] * Wl2[c];
    }
    #pragma unroll
    for (int off = 16; off > 0; off >>= 1)
        a += __shfl_xor_sync(0xffffffffu, a, off);
    if (lane == 0)
        g_sci[warp] = 1.f / (1.f + expf(-(a + bl2[0])));
}

__global__ void sci_writeout_kernel(float* __restrict__ out, int n)
{
    int i = blockIdx.x * blockDim.x + threadIdx.x;
    if (i < n) {
        float v = g_sci[i];
        out[i] = v;
        out[n + i] = v;
        out[2L * n + i] = v;
    }
}

// ---------------------------------------------------------------------------
// Launch
// ---------------------------------------------------------------------------
extern "C" void kernel_launch(void* const* d_in, const int* in_sizes, int n_in,
                              void* d_out, int out_size)
{
    const float* discrete_x = (const float*)d_in[0];
    const float* continous_x = (const float*)d_in[1];
    const float* Wd  = (const float*)d_in[2];
    const float* bd  = (const float*)d_in[3];
    const float* Wc1 = (const float*)d_in[4];
    const float* bc1 = (const float*)d_in[5];
    const float* Wc2 = (const float*)d_in[6];
    const float* bc2 = (const float*)d_in[7];
    const float* Wg0 = (const float*)d_in[8];
    const float* bg0 = (const float*)d_in[9];
    const float* Wg1 = (const float*)d_in[10];
    const float* bg1 = (const float*)d_in[11];
    const float* Wg2 = (const float*)d_in[12];
    const float* bg2 = (const float*)d_in[13];
    const float* Wf  = (const float*)d_in[14];
    const float* bf  = (const float*)d_in[15];
    const float* Wl1 = (const float*)d_in[16];
    const float* bl1 = (const float*)d_in[17];
    const float* Wl2 = (const float*)d_in[18];
    const float* bl2 = (const float*)d_in[19];
    const void*  edge_index = d_in[20];

    const int n = in_sizes[0] / DDISC;       // 50000
    const int e = in_sizes[20] / 2;          // 800000

    float *pY, *pS;
    cudaGetSymbolAddress((void**)&pY, g_Y);
    cudaGetSymbolAddress((void**)&pS, g_S);
    __nv_bfloat16 *pAh, *pAl, *pGh, *pGl, *pHh, *pHl, *pDh, *pDl, *pWth, *pWtl;
    cudaGetSymbolAddress((void**)&pAh, g_Ah);
    cudaGetSymbolAddress((void**)&pAl, g_Al);
    cudaGetSymbolAddress((void**)&pGh, g_Gh);
    cudaGetSymbolAddress((void**)&pGl, g_Gl);
    cudaGetSymbolAddress((void**)&pHh, g_Hh);
    cudaGetSymbolAddress((void**)&pHl, g_Hl);
    cudaGetSymbolAddress((void**)&pDh, g_Dh);
    cudaGetSymbolAddress((void**)&pDl, g_Dl);
    cudaGetSymbolAddress((void**)&pWth, g_Wth);
    cudaGetSymbolAddress((void**)&pWtl, g_Wtl);

    cudaFuncSetAttribute(mma_gemm_kernel<0,0>, cudaFuncAttributeMaxDynamicSharedMemorySize, 3*STG);
    cudaFuncSetAttribute(mma_gemm_kernel<1,0>, cudaFuncAttributeMaxDynamicSharedMemorySize, 3*STG);
    cudaFuncSetAttribute(mma_gemm_kernel<1,1>, cudaFuncAttributeMaxDynamicSharedMemorySize, 3*STG);
    cudaFuncSetAttribute(mma_gemm_kernel<1,2>, cudaFuncAttributeMaxDynamicSharedMemorySize, 3*STG);

    dim3 blk(256);
    const int mtiles = (n + 127) / 128;   // 391
    float* outf = (float*)d_out;
    long tot = (long)n * HID;

    // ---- graph preprocessing ----
    probe_kernel<<<1, 256>>>((const int*)edge_index, 2 * e);
    zero_cnt_kernel<<<(n + 255) / 256, blk>>>(n);
    count_kernel<<<(e + 255) / 256, blk>>>(edge_index, e, n);
    dinv_kernel<<<(n + 255) / 256, blk>>>(n);
    scan_kernel<<<1, 1024>>>(n);
    fill_kernel<<<(e + 255) / 256, blk>>>(edge_index, e, n);

    // ---- discrete embeddings via HMMA (K=64), split outputs ----
    {
        long nd = (long)n * DDISC;
        splitA_kernel<<<(unsigned)((nd + 255) / 256), blk>>>(discrete_x, pDh, pDl, nd);
        splitWT_kernel<<<(DDISC * EMB + 255) / 256, blk>>>(Wd, pWth, pWtl, DDISC, EMB);
        mma_gemm_kernel<1,1><<<dim3(2, mtiles), blk, 3*STG>>>(
            pDh, pDl, pWth, pWtl, bd,
            (float*)nullptr, (float*)nullptr, 0, pAh, pAl, CAT, n, DDISC, EMB);
        splitWT_kernel<<<(DDISC * EMB + 255) / 256, blk>>>(Wg0, pWth, pWtl, DDISC, EMB);
        mma_gemm_kernel<1,1><<<dim3(2, mtiles), blk, 3*STG>>>(
            pDh, pDl, pWth, pWtl, bg0,
            (float*)nullptr, (float*)nullptr, 0, pGh, pGl, EMB, n, DDISC, EMB);
    }

    // ---- continuous embeddings (SIMT, K=13), split outputs into concat ----
    {
        dim3 grid((EMB + 127) / 128, mtiles);
        sgemm_split_kernel<<<grid, blk>>>(continous_x,         3*DCONT, Wc1, bc1,
                                          pAh + EMB, pAl + EMB, CAT, n, DCONT, EMB);
        sgemm_split_kernel<<<grid, blk>>>(continous_x + DCONT, 3*DCONT, Wc2, bc2,
                                          pAh + 2*EMB, pAl + 2*EMB, CAT, n, DCONT, EMB);
    }

    // ---- GCN conv 1 ----
    {
        splitWT_kernel<<<(EMB * EMB + 255) / 256, blk>>>(Wg1, pWth, pWtl, EMB, EMB);
        mma_gemm_kernel<0,0><<<dim3(2, mtiles), blk, 3*STG>>>(
            pGh, pGl, pWth, pWtl, (const float*)nullptr,
            pY, (float*)nullptr, EMB, (__nv_bfloat16*)nullptr, (__nv_bfloat16*)nullptr, 0,
            n, EMB, EMB);
        agg_kernel<<<(n * 32 + 255) / 256, blk>>>(pY, bg1, pGh, pGl, EMB, n);

        // ---- GCN conv 2 ----
        splitWT_kernel<<<(EMB * EMB + 255) / 256, blk>>>(Wg2, pWth, pWtl, EMB, EMB);
        mma_gemm_kernel<0,0><<<dim3(2, mtiles), blk, 3*STG>>>(
            pGh, pGl, pWth, pWtl, (const float*)nullptr,
            pY, (float*)nullptr, EMB, (__nv_bfloat16*)nullptr, (__nv_bfloat16*)nullptr, 0,
            n, EMB, EMB);
        agg_kernel<<<(n * 32 + 255) / 256, blk>>>(pY, bg2, pAh + 3*EMB, pAl + 3*EMB, CAT, n);
    }

    // ---- fusion MLP: H = lrelu(X4 @ Wf + bf) -> split + dual fp32 into d_out ----
    {
        splitWT_kernel<<<(CAT * HID + 255) / 256, blk>>>(Wf, pWth, pWtl, CAT, HID);
        mma_gemm_kernel<1,2><<<dim3(4, mtiles), blk, 3*STG>>>(
            pAh, pAl, pWth, pWtl, bf,
            outf + 3L * n, outf + 3L * n + tot, HID, pHh, pHl, HID, n, CAT, HID);
        splitWT_kernel<<<(HID * EMB + 255) / 256, blk>>>(Wl1, pWth, pWtl, HID, EMB);
        mma_gemm_kernel<1,0><<<dim3(2, mtiles), blk, 3*STG>>>(
            pHh, pHl, pWth, pWtl, bl1,
            pS, (float*)nullptr, EMB, (__nv_bfloat16*)nullptr, (__nv_bfloat16*)nullptr, 0,
            n, HID, EMB);
    }

    // ---- final sigmoid head + s_ci writeout ----
    final_kernel<<<(n * 32 + 255) / 256, blk>>>(Wl2, bl2, n);
    sci_writeout_kernel<<<(n + 255) / 256, blk>>>(outf, n);
}

// round 8
// speedup vs baseline: 1.0547x; 1.0547x over previous
#include <cuda_runtime.h>
#include <cuda_bf16.h>
#include <math.h>
#include <stdint.h>

// ---------------------------------------------------------------------------
// Problem constants
// ---------------------------------------------------------------------------
#define NN    50000
#define EE    800000
#define EMB   256
#define HID   512
#define DDISC 64
#define DCONT 13
#define CAT   (4*EMB)      // 1024
#define SLOPE 0.01f

// transposed-weight pool offsets ([N,K] row-major, bf16)
#define OW_DG  0            // combined [512,64]: rows 0-255 Wd, 256-511 Wg0
#define OW_G1  32768        // [256,256]
#define OW_G2  98304        // [256,256]
#define OW_F   163840       // [512,1024]
#define OW_L1  688128       // [256,512]
#define OW_TOT 819200

// ---------------------------------------------------------------------------
// Scratch — __device__ globals (no cudaMalloc allowed)
// ---------------------------------------------------------------------------
__device__ float g_Y [(long)NN*EMB];     // conv pre-aggregation (fp32)
__device__ float g_S [(long)NN*EMB];     // s
__device__ float g_sci[NN];
__device__ float g_dinv[NN];
__device__ float g_b2[2*EMB];            // concat(bd, bg0)
__device__ int   g_cnt[NN];
__device__ int   g_rowptr[NN+1];
__device__ int   g_cursor[NN];
__device__ int   g_colsrc[EE];
__device__ int   g_is64;

// bf16 split buffers (hi/lo)
__device__ __align__(16) __nv_bfloat16 g_Ah[(long)NN*CAT];   // concat split
__device__ __align__(16) __nv_bfloat16 g_Al[(long)NN*CAT];
__device__ __align__(16) __nv_bfloat16 g_Gh[(long)NN*EMB];   // gcn activation split
__device__ __align__(16) __nv_bfloat16 g_Gl[(long)NN*EMB];
__device__ __align__(16) __nv_bfloat16 g_Hh[(long)NN*HID];   // h_ci split
__device__ __align__(16) __nv_bfloat16 g_Hl[(long)NN*HID];
__device__ __align__(16) __nv_bfloat16 g_Dh[(long)NN*DDISC]; // discrete_x split
__device__ __align__(16) __nv_bfloat16 g_Dl[(long)NN*DDISC];
__device__ __align__(16) __nv_bfloat16 g_Wth[OW_TOT];        // transposed weight pool
__device__ __align__(16) __nv_bfloat16 g_Wtl[OW_TOT];

// ---------------------------------------------------------------------------
// asm helpers (base ISA only — must compile for compute_103)
// ---------------------------------------------------------------------------
__device__ __forceinline__ uint32_t smem_u32(const void* p) {
    uint32_t a;
    asm("{ .reg .u64 t; cvta.to.shared.u64 t, %1; cvt.u32.u64 %0, t; }" : "=r"(a) : "l"(p));
    return a;
}
__device__ __forceinline__ void ldsm4(uint32_t& r0, uint32_t& r1, uint32_t& r2, uint32_t& r3,
                                      uint32_t addr) {
    asm volatile("ldmatrix.sync.aligned.m8n8.x4.shared.b16 {%0,%1,%2,%3}, [%4];"
                 : "=r"(r0), "=r"(r1), "=r"(r2), "=r"(r3) : "r"(addr));
}
__device__ __forceinline__ void mma16816(float* c, const uint32_t* a, const uint32_t* b) {
    asm volatile(
        "mma.sync.aligned.m16n8k16.row.col.f32.bf16.bf16.f32 "
        "{%0,%1,%2,%3}, {%4,%5,%6,%7}, {%8,%9}, {%0,%1,%2,%3};"
        : "+f"(c[0]), "+f"(c[1]), "+f"(c[2]), "+f"(c[3])
        : "r"(a[0]), "r"(a[1]), "r"(a[2]), "r"(a[3]), "r"(b[0]), "r"(b[1]));
}
__device__ __forceinline__ void cp16(uint32_t dst, const void* src, int sz) {
    asm volatile("cp.async.cg.shared.global [%0], [%1], 16, %2;"
                 :: "r"(dst), "l"(src), "r"(sz) : "memory");
}
__device__ __forceinline__ void cp_commit() {
    asm volatile("cp.async.commit_group;" ::: "memory");
}
__device__ __forceinline__ void cp_wait1() {
    asm volatile("cp.async.wait_group 1;" ::: "memory");
}
__device__ __forceinline__ void cp_wait0() {
    asm volatile("cp.async.wait_group 0;" ::: "memory");
}
// byte offset inside a [rows][32 halfs] tile (row stride 64B, 16B-chunk swizzle)
__device__ __forceinline__ uint32_t swa(int r, int ci) {
    return (uint32_t)(r * 64 + ((ci ^ (r & 3) ^ ((r >> 2) & 1)) * 16));
}
__device__ __forceinline__ void split_store(__nv_bfloat16* H, __nv_bfloat16* L,
                                            size_t off, float v0, float v1) {
    __nv_bfloat16 h0 = __float2bfloat16(v0);
    __nv_bfloat16 h1 = __float2bfloat16(v1);
    __nv_bfloat16 l0 = __float2bfloat16(v0 - __bfloat162float(h0));
    __nv_bfloat16 l1 = __float2bfloat16(v1 - __bfloat162float(h1));
    *(__nv_bfloat162*)(H + off) = __nv_bfloat162(h0, h1);
    *(__nv_bfloat162*)(L + off) = __nv_bfloat162(l0, l1);
}

// ---------------------------------------------------------------------------
// bf16x3 HMMA GEMM, cp.async double-buffered (2 stages — R5 known-good).
// C = act(A @ W + bias). A split [M,K] row-major; W split transposed [N,K].
// CTA tile 128x128, 8 warps (warp tile 32x64), K-chunk 32, K%32==0, N%128==0.
// MODE 0: write Cf fp32.
// MODE 2: write split (Ch,Cl) + fp32 into Cf AND Cf2.
// MODE 3: dual split dest — cols < 256 -> (Ch,Cl,lds); cols >= 256 -> (Ch2,Cl2,lds2).
// Dynamic smem: 2 stages x 32KB = 64KB.
// ---------------------------------------------------------------------------
#define STG 32768
template<int ACT, int MODE>
__global__ __launch_bounds__(256, 2)
void mma_gemm_kernel(const __nv_bfloat16* __restrict__ Ah,
                     const __nv_bfloat16* __restrict__ Al,
                     const __nv_bfloat16* __restrict__ Bh,   // [N,K]
                     const __nv_bfloat16* __restrict__ Bl,
                     const float* __restrict__ bias,
                     float* __restrict__ Cf, float* __restrict__ Cf2, int ldf,
                     __nv_bfloat16* __restrict__ Ch, __nv_bfloat16* __restrict__ Cl, int lds,
                     __nv_bfloat16* __restrict__ Ch2, __nv_bfloat16* __restrict__ Cl2, int lds2,
                     int M, int K, int N)
{
    extern __shared__ char sm[];
    const uint32_t sb = smem_u32(sm);
    const uint32_t oAH = 0, oAL = 8192, oBH = 16384, oBL = 24576;

    int tid = threadIdx.x;
    int wid = tid >> 5;
    int lane = tid & 31;
    int wm = wid & 3;
    int wn = wid >> 2;
    int row0 = blockIdx.y * 128;
    int col0 = blockIdx.x * 128;

    float acc[2][8][4];
    #pragma unroll
    for (int i = 0; i < 2; i++)
        #pragma unroll
        for (int j = 0; j < 8; j++)
            #pragma unroll
            for (int q = 0; q < 4; q++) acc[i][j][q] = 0.f;

    int Lg = lane >> 3;
    int Lr = lane & 7;
    const int nchunks = K >> 5;

    auto prefetch = [&](int ch, int stage) {
        int k0 = ch << 5;
        uint32_t base = sb + stage * STG;
        #pragma unroll
        for (int it = 0; it < 2; it++) {
            int idx = tid + it * 256;          // 0..511
            int r = idx >> 2, ci = idx & 3;
            uint32_t sw = swa(r, ci);
            int gr = row0 + r;
            int ok = (gr < M) ? 16 : 0;
            size_t ga = (size_t)(ok ? gr : 0) * K + k0 + ci * 8;
            cp16(base + oAH + sw, Ah + ga, ok);
            cp16(base + oAL + sw, Al + ga, ok);
            size_t gb = (size_t)(col0 + r) * K + k0 + ci * 8;
            cp16(base + oBH + sw, Bh + gb, 16);
            cp16(base + oBL + sw, Bl + gb, 16);
        }
        cp_commit();
    };

    prefetch(0, 0);
    for (int ch = 0; ch < nchunks; ch++) {
        if (ch + 1 < nchunks) {
            prefetch(ch + 1, (ch + 1) & 1);
            cp_wait1();
        } else {
            cp_wait0();
        }
        __syncthreads();
        uint32_t base = sb + (ch & 1) * STG;

        #pragma unroll
        for (int ks = 0; ks < 2; ks++) {
            uint32_t ah[2][4], al[2][4];
            #pragma unroll
            for (int ma = 0; ma < 2; ma++) {
                int ar = wm * 32 + ma * 16 + Lr + (Lg & 1) * 8;
                int ac = ks * 2 + (Lg >> 1);
                uint32_t sw = swa(ar, ac);
                ldsm4(ah[ma][0], ah[ma][1], ah[ma][2], ah[ma][3], base + oAH + sw);
                ldsm4(al[ma][0], al[ma][1], al[ma][2], al[ma][3], base + oAL + sw);
            }
            #pragma unroll
            for (int g = 0; g < 4; g++) {
                int br = wn * 64 + g * 16 + Lr + (Lg >> 1) * 8;
                int bc = ks * 2 + (Lg & 1);
                uint32_t sw = swa(br, bc);
                uint32_t bh[4], bl[4];
                ldsm4(bh[0], bh[1], bh[2], bh[3], base + oBH + sw);
                ldsm4(bl[0], bl[1], bl[2], bl[3], base + oBL + sw);
                #pragma unroll
                for (int ma = 0; ma < 2; ma++) {
                    mma16816(acc[ma][g*2+0], ah[ma], bh + 0);
                    mma16816(acc[ma][g*2+1], ah[ma], bh + 2);
                    mma16816(acc[ma][g*2+0], ah[ma], bl + 0);
                    mma16816(acc[ma][g*2+1], ah[ma], bl + 2);
                    mma16816(acc[ma][g*2+0], al[ma], bh + 0);
                    mma16816(acc[ma][g*2+1], al[ma], bh + 2);
                }
            }
        }
        __syncthreads();
    }

    // ---- epilogue ----
    int rbase = row0 + wm * 32 + (lane >> 2);
    int cbase = col0 + wn * 64 + (lane & 3) * 2;
    #pragma unroll
    for (int ma = 0; ma < 2; ma++) {
        #pragma unroll
        for (int na = 0; na < 8; na++) {
            int gc = cbase + na * 8;
            float b0 = bias ? bias[gc] : 0.f;
            float b1 = bias ? bias[gc + 1] : 0.f;
            #pragma unroll
            for (int h = 0; h < 2; h++) {
                int gr = rbase + ma * 16 + h * 8;
                if (gr < M) {
                    float v0 = acc[ma][na][h * 2 + 0] + b0;
                    float v1 = acc[ma][na][h * 2 + 1] + b1;
                    if (ACT == 1) {
                        v0 = v0 > 0.f ? v0 : SLOPE * v0;
                        v1 = v1 > 0.f ? v1 : SLOPE * v1;
                    }
                    if (MODE == 0 || MODE == 2) {
                        *(float2*)(Cf + (size_t)gr * ldf + gc) = make_float2(v0, v1);
                        if (MODE == 2)
                            *(float2*)(Cf2 + (size_t)gr * ldf + gc) = make_float2(v0, v1);
                    }
                    if (MODE == 2)
                        split_store(Ch, Cl, (size_t)gr * lds + gc, v0, v1);
                    if (MODE == 3) {
                        if (gc < 256)
                            split_store(Ch, Cl, (size_t)gr * lds + gc, v0, v1);
                        else
                            split_store(Ch2, Cl2, (size_t)gr * lds2 + (gc - 256), v0, v1);
                    }
                }
            }
        }
    }
}

// ---------------------------------------------------------------------------
// input feature split (fp32 -> bf16 hi/lo)
// ---------------------------------------------------------------------------
__global__ void splitA_kernel(const float* __restrict__ X,
                              __nv_bfloat16* __restrict__ H,
                              __nv_bfloat16* __restrict__ L, long n)
{
    long i = (long)blockIdx.x * blockDim.x + threadIdx.x;
    if (i >= n) return;
    float a = X[i];
    __nv_bfloat16 h = __float2bfloat16(a);
    H[i] = h;
    L[i] = __float2bfloat16(a - __bfloat162float(h));
}

// ---------------------------------------------------------------------------
// ONE kernel: transpose+split ALL weights into the pool, plus bias concat.
// Segment s covers src W[K,N] -> pool[off + n*K + k].
// ---------------------------------------------------------------------------
__global__ void splitW_all_kernel(const float* __restrict__ Wd,  const float* __restrict__ Wg0,
                                  const float* __restrict__ Wg1, const float* __restrict__ Wg2,
                                  const float* __restrict__ Wf,  const float* __restrict__ Wl1,
                                  const float* __restrict__ bd,  const float* __restrict__ bg0)
{
    const int c0 = DDISC*EMB;            // 16384
    const int c1 = c0 + DDISC*EMB;       // 32768
    const int c2 = c1 + EMB*EMB;         // 98304
    const int c3 = c2 + EMB*EMB;         // 163840
    const int c4 = c3 + CAT*HID;         // 688128
    const int c5 = c4 + HID*EMB;         // 819200
    for (long i = (long)blockIdx.x * blockDim.x + threadIdx.x;
         i < c5 + 2*EMB; i += (long)gridDim.x * blockDim.x) {
        if (i >= c5) {                   // bias concat tail
            int j = (int)(i - c5);
            g_b2[j] = (j < EMB) ? bd[j] : bg0[j - EMB];
            continue;
        }
        const float* W; long loc, off; int K, N;
        if (i < c0)      { W = Wd;  loc = i;      off = OW_DG;           K = DDISC; N = EMB; }
        else if (i < c1) { W = Wg0; loc = i - c0; off = OW_DG + (long)EMB*DDISC; K = DDISC; N = EMB; }
        else if (i < c2) { W = Wg1; loc = i - c1; off = OW_G1; K = EMB; N = EMB; }
        else if (i < c3) { W = Wg2; loc = i - c2; off = OW_G2; K = EMB; N = EMB; }
        else if (i < c4) { W = Wf;  loc = i - c3; off = OW_F;  K = CAT; N = HID; }
        else             { W = Wl1; loc = i - c4; off = OW_L1; K = HID; N = EMB; }
        int k = (int)(loc / N), nn = (int)(loc % N);
        float a = W[loc];
        __nv_bfloat16 h = __float2bfloat16(a);
        long o = off + (long)nn * K + k;
        g_Wth[o] = h;
        g_Wtl[o] = __float2bfloat16(a - __bfloat162float(h));
    }
}

// ---------------------------------------------------------------------------
// Edge dtype probe + graph preprocessing
// ---------------------------------------------------------------------------
__global__ void probe_kernel(const int* __restrict__ ei32, int nwords)
{
    __shared__ int nz;
    if (threadIdx.x == 0) nz = 0;
    __syncthreads();
    int lim = nwords < 4096 ? nwords : 4096;
    for (int i = 1 + 2 * threadIdx.x; i < lim; i += 2 * blockDim.x)
        if (ei32[i] != 0) atomicAdd(&nz, 1);
    __syncthreads();
    if (threadIdx.x == 0) g_is64 = (nz == 0) ? 1 : 0;
}

__device__ __forceinline__ int edge_at(const void* base, long i, int is64)
{
    return is64 ? (int)((const long long*)base)[i] : ((const int*)base)[i];
}

__global__ void zero_cnt_kernel(int n) {
    int i = blockIdx.x * blockDim.x + threadIdx.x;
    if (i < n) g_cnt[i] = 0;
}

__global__ void count_kernel(const void* __restrict__ ei, int e, int n) {
    int i = blockIdx.x * blockDim.x + threadIdx.x;
    if (i >= e) return;
    int is64 = g_is64;
    int d = edge_at(ei, (long)e + i, is64);
    if ((unsigned)d < (unsigned)n) atomicAdd(&g_cnt[d], 1);
}

__global__ void dinv_kernel(int n) {
    int i = blockIdx.x * blockDim.x + threadIdx.x;
    if (i < n) g_dinv[i] = rsqrtf((float)(g_cnt[i] + 1));
}

// fast single-block scan: serial per-thread segments + one 1024-wide scan
__global__ void scan_kernel(int n) {
    __shared__ int part[1024];
    int tid = threadIdx.x;
    int per = (n + 1023) >> 10;
    int beg = tid * per;
    int end = beg + per < n ? beg + per : n;
    int s = 0;
    for (int i = beg; i < end; i++) s += g_cnt[i];
    part[tid] = s;
    __syncthreads();
    for (int off = 1; off < 1024; off <<= 1) {
        int t = (tid >= off) ? part[tid - off] : 0;
        __syncthreads();
        part[tid] += t;
        __syncthreads();
    }
    int run = part[tid] - s;
    for (int i = beg; i < end; i++) {
        int v = g_cnt[i];
        g_rowptr[i] = run;
        g_cursor[i] = run;
        run += v;
    }
    if (tid == 1023) g_rowptr[n] = run;
}

__global__ void fill_kernel(const void* __restrict__ ei, int e, int n) {
    int i = blockIdx.x * blockDim.x + threadIdx.x;
    if (i >= e) return;
    int is64 = g_is64;
    int s = edge_at(ei, i, is64);
    int d = edge_at(ei, (long)e + i, is64);
    if ((unsigned)d < (unsigned)n && (unsigned)s < (unsigned)n) {
        int pos = atomicAdd(&g_cursor[d], 1);
        if (pos < EE) g_colsrc[pos] = s;
    }
}

// ---------------------------------------------------------------------------
// Merged continuous embeds (K=13), one launch: half = blockIdx.x>>1.
// Writes bf16 split into concat buffer at column offset (1+half)*EMB.
// ---------------------------------------------------------------------------
__global__ __launch_bounds__(256)
void cont_embed_kernel(const float* __restrict__ X,   // continous_x [M, 39]
                       const float* __restrict__ Wc1, const float* __restrict__ bc1,
                       const float* __restrict__ Wc2, const float* __restrict__ bc2,
                       __nv_bfloat16* __restrict__ Ch, __nv_bfloat16* __restrict__ Cl,
                       int M)
{
    const int K = DCONT, NC = EMB, lda = 3*DCONT;
    int half = blockIdx.x >> 1;
    int col0 = (blockIdx.x & 1) * 128;
    const float* A = X + half * DCONT;
    const float* W = half ? Wc2 : Wc1;
    const float* bias = half ? bc2 : bc1;
    __nv_bfloat16* OH = Ch + (1 + half) * EMB;
    __nv_bfloat16* OL = Cl + (1 + half) * EMB;

    __shared__ float As[16][128];
    __shared__ float Ws[16][128];

    int tid = threadIdx.x;
    int tx = tid & 15;
    int ty = tid >> 4;
    int row0 = blockIdx.y * 128;

    float acc[8][8];
    #pragma unroll
    for (int i = 0; i < 8; i++)
        #pragma unroll
        for (int j = 0; j < 8; j++) acc[i][j] = 0.f;

    // load full K=13 (pad to 16) in one shot
    {
        int a_row = tid >> 1;
        int a_col = (tid & 1) * 8;
        #pragma unroll
        for (int j = 0; j < 8; j++) {
            int r = row0 + a_row, c = a_col + j;
            As[a_col + j][a_row] = (r < M && c < K) ? A[(long)r * lda + c] : 0.f;
        }
        int w_k = tid >> 5;            // 0..7 (two rounds for 16)
        int w_n = (tid & 31) * 4;
        #pragma unroll
        for (int rep = 0; rep < 2; rep++) {
            int kk = w_k + rep * 8;
            #pragma unroll
            for (int j = 0; j < 4; j++) {
                int nn = col0 + w_n + j;
                Ws[kk][w_n + j] = (kk < K) ? W[(long)kk * NC + nn] : 0.f;
            }
        }
    }
    __syncthreads();
    #pragma unroll
    for (int k = 0; k < 13; k++) {
        float a[8], b[8];
        #pragma unroll
        for (int i = 0; i < 8; i++) a[i] = As[k][ty * 8 + i];
        #pragma unroll
        for (int j = 0; j < 8; j++) b[j] = Ws[k][tx * 8 + j];
        #pragma unroll
        for (int i = 0; i < 8; i++)
            #pragma unroll
            for (int j = 0; j < 8; j++)
                acc[i][j] += a[i] * b[j];
    }

    #pragma unroll
    for (int i = 0; i < 8; i++) {
        int r = row0 + ty * 8 + i;
        if (r >= M) continue;
        #pragma unroll
        for (int j = 0; j < 8; j += 2) {
            int c = col0 + tx * 8 + j;
            float v0 = acc[i][j] + bias[c];
            float v1 = acc[i][j + 1] + bias[c + 1];
            v0 = v0 > 0.f ? v0 : SLOPE * v0;
            v1 = v1 > 0.f ? v1 : SLOPE * v1;
            split_store(OH, OL, (size_t)r * CAT + c, v0, v1);
        }
    }
}

// ---------------------------------------------------------------------------
// GCN aggregation (one warp per node), float4 gathers, writes bf16 split.
// ---------------------------------------------------------------------------
__global__ __launch_bounds__(256)
void agg_kernel(const float* __restrict__ Y, const float* __restrict__ bias,
                __nv_bfloat16* __restrict__ Oh, __nv_bfloat16* __restrict__ Ol,
                int ldc, int n)
{
    int warp = (blockIdx.x * blockDim.x + threadIdx.x) >> 5;
    int lane = threadIdx.x & 31;
    if (warp >= n) return;
    int beg = g_rowptr[warp], end = g_rowptr[warp + 1];
    int c0 = lane * 8;
    float4 a0 = make_float4(0.f, 0.f, 0.f, 0.f);
    float4 a1 = make_float4(0.f, 0.f, 0.f, 0.f);
    for (int e = beg; e < end; e++) {
        int s = g_colsrc[e];
        float w = g_dinv[s];
        const float4* yr = (const float4*)(Y + (size_t)s * EMB + c0);
        float4 y0 = yr[0], y1 = yr[1];
        a0.x += y0.x * w; a0.y += y0.y * w; a0.z += y0.z * w; a0.w += y0.w * w;
        a1.x += y1.x * w; a1.y += y1.y * w; a1.z += y1.z * w; a1.w += y1.w * w;
    }
    float di = g_dinv[warp];
    float dii = di * di;
    const float4* ys = (const float4*)(Y + (size_t)warp * EMB + c0);
    float4 s0 = ys[0], s1 = ys[1];
    const float4* bp = (const float4*)(bias + c0);
    float4 b0 = bp[0], b1 = bp[1];
    float v[8];
    v[0] = di * a0.x + dii * s0.x + b0.x;
    v[1] = di * a0.y + dii * s0.y + b0.y;
    v[2] = di * a0.z + dii * s0.z + b0.z;
    v[3] = di * a0.w + dii * s0.w + b0.w;
    v[4] = di * a1.x + dii * s1.x + b1.x;
    v[5] = di * a1.y + dii * s1.y + b1.y;
    v[6] = di * a1.z + dii * s1.z + b1.z;
    v[7] = di * a1.w + dii * s1.w + b1.w;
    size_t ob = (size_t)warp * ldc + c0;
    #pragma unroll
    for (int j = 0; j < 8; j += 2) {
        float v0 = v[j] > 0.f ? v[j] : SLOPE * v[j];
        float v1 = v[j+1] > 0.f ? v[j+1] : SLOPE * v[j+1];
        split_store(Oh, Ol, ob + j, v0, v1);
    }
}

// ---------------------------------------------------------------------------
// Final sigmoid head + small s_ci writeout
// ---------------------------------------------------------------------------
__global__ __launch_bounds__(256)
void final_kernel(const float* __restrict__ Wl2, const float* __restrict__ bl2, int n)
{
    int warp = (blockIdx.x * blockDim.x + threadIdx.x) >> 5;
    int lane = threadIdx.x & 31;
    if (warp >= n) return;
    const float* sr = g_S + (long)warp * EMB;
    float a = 0.f;
    #pragma unroll
    for (int j = 0; j < 8; j++) {
        int c = lane + 32 * j;
        a += sr[c] * Wl2[c];
    }
    #pragma unroll
    for (int off = 16; off > 0; off >>= 1)
        a += __shfl_xor_sync(0xffffffffu, a, off);
    if (lane == 0)
        g_sci[warp] = 1.f / (1.f + expf(-(a + bl2[0])));
}

__global__ void sci_writeout_kernel(float* __restrict__ out, int n)
{
    int i = blockIdx.x * blockDim.x + threadIdx.x;
    if (i < n) {
        float v = g_sci[i];
        out[i] = v;
        out[n + i] = v;
        out[2L * n + i] = v;
    }
}

// ---------------------------------------------------------------------------
// Launch
// ---------------------------------------------------------------------------
extern "C" void kernel_launch(void* const* d_in, const int* in_sizes, int n_in,
                              void* d_out, int out_size)
{
    const float* discrete_x = (const float*)d_in[0];
    const float* continous_x = (const float*)d_in[1];
    const float* Wd  = (const float*)d_in[2];
    const float* Wc1 = (const float*)d_in[4];
    const float* bc1 = (const float*)d_in[5];
    const float* Wc2 = (const float*)d_in[6];
    const float* bc2 = (const float*)d_in[7];
    const float* Wg0 = (const float*)d_in[8];
    const float* Wg1 = (const float*)d_in[10];
    const float* bg1 = (const float*)d_in[11];
    const float* Wg2 = (const float*)d_in[12];
    const float* bg2 = (const float*)d_in[13];
    const float* Wf  = (const float*)d_in[14];
    const float* bf  = (const float*)d_in[15];
    const float* Wl1 = (const float*)d_in[16];
    const float* bl1 = (const float*)d_in[17];
    const float* Wl2 = (const float*)d_in[18];
    const float* bl2 = (const float*)d_in[19];
    const float* bd  = (const float*)d_in[3];
    const float* bg0 = (const float*)d_in[9];
    const void*  edge_index = d_in[20];

    const int n = in_sizes[0] / DDISC;       // 50000
    const int e = in_sizes[20] / 2;          // 800000

    float *pY, *pS, *pB2;
    cudaGetSymbolAddress((void**)&pY, g_Y);
    cudaGetSymbolAddress((void**)&pS, g_S);
    cudaGetSymbolAddress((void**)&pB2, g_b2);
    __nv_bfloat16 *pAh, *pAl, *pGh, *pGl, *pHh, *pHl, *pDh, *pDl, *pWth, *pWtl;
    cudaGetSymbolAddress((void**)&pAh, g_Ah);
    cudaGetSymbolAddress((void**)&pAl, g_Al);
    cudaGetSymbolAddress((void**)&pGh, g_Gh);
    cudaGetSymbolAddress((void**)&pGl, g_Gl);
    cudaGetSymbolAddress((void**)&pHh, g_Hh);
    cudaGetSymbolAddress((void**)&pHl, g_Hl);
    cudaGetSymbolAddress((void**)&pDh, g_Dh);
    cudaGetSymbolAddress((void**)&pDl, g_Dl);
    cudaGetSymbolAddress((void**)&pWth, g_Wth);
    cudaGetSymbolAddress((void**)&pWtl, g_Wtl);

    cudaFuncSetAttribute(mma_gemm_kernel<0,0>, cudaFuncAttributeMaxDynamicSharedMemorySize, 2*STG);
    cudaFuncSetAttribute(mma_gemm_kernel<1,0>, cudaFuncAttributeMaxDynamicSharedMemorySize, 2*STG);
    cudaFuncSetAttribute(mma_gemm_kernel<1,2>, cudaFuncAttributeMaxDynamicSharedMemorySize, 2*STG);
    cudaFuncSetAttribute(mma_gemm_kernel<1,3>, cudaFuncAttributeMaxDynamicSharedMemorySize, 2*STG);

    dim3 blk(256);
    const int mtiles = (n + 127) / 128;   // 391
    float* outf = (float*)d_out;
    long tot = (long)n * HID;
    __nv_bfloat16* nb = nullptr;
    float* nf = nullptr;

    // ---- graph preprocessing + weight prep ----
    probe_kernel<<<1, 256>>>((const int*)edge_index, 2 * e);
    zero_cnt_kernel<<<(n + 255) / 256, blk>>>(n);
    count_kernel<<<(e + 255) / 256, blk>>>(edge_index, e, n);
    dinv_kernel<<<(n + 255) / 256, blk>>>(n);
    scan_kernel<<<1, 1024>>>(n);
    fill_kernel<<<(e + 255) / 256, blk>>>(edge_index, e, n);
    splitW_all_kernel<<<592, blk>>>(Wd, Wg0, Wg1, Wg2, Wf, Wl1, bd, bg0);
    {
        long nd = (long)n * DDISC;
        splitA_kernel<<<(unsigned)((nd + 255) / 256), blk>>>(discrete_x, pDh, pDl, nd);
    }

    // ---- merged discrete embeddings: one N=512 GEMM -> (x_d cols | x_g0) ----
    mma_gemm_kernel<1,3><<<dim3(4, mtiles), blk, 2*STG>>>(
        pDh, pDl, pWth + OW_DG, pWtl + OW_DG, pB2,
        nf, nf, 0, pAh, pAl, CAT, pGh, pGl, EMB, n, DDISC, 512);

    // ---- merged continuous embeds (one launch) ----
    cont_embed_kernel<<<dim3(4, mtiles), blk>>>(continous_x, Wc1, bc1, Wc2, bc2,
                                                pAh, pAl, n);

    // ---- GCN conv 1 ----
    mma_gemm_kernel<0,0><<<dim3(2, mtiles), blk, 2*STG>>>(
        pGh, pGl, pWth + OW_G1, pWtl + OW_G1, nf,
        pY, nf, EMB, nb, nb, 0, nb, nb, 0, n, EMB, EMB);
    agg_kernel<<<(n * 32 + 255) / 256, blk>>>(pY, bg1, pGh, pGl, EMB, n);

    // ---- GCN conv 2 ----
    mma_gemm_kernel<0,0><<<dim3(2, mtiles), blk, 2*STG>>>(
        pGh, pGl, pWth + OW_G2, pWtl + OW_G2, nf,
        pY, nf, EMB, nb, nb, 0, nb, nb, 0, n, EMB, EMB);
    agg_kernel<<<(n * 32 + 255) / 256, blk>>>(pY, bg2, pAh + 3*EMB, pAl + 3*EMB, CAT, n);

    // ---- fusion MLP: H -> split + dual fp32 into d_out ----
    mma_gemm_kernel<1,2><<<dim3(4, mtiles), blk, 2*STG>>>(
        pAh, pAl, pWth + OW_F, pWtl + OW_F, bf,
        outf + 3L * n, outf + 3L * n + tot, HID, pHh, pHl, HID, nb, nb, 0, n, CAT, HID);
    mma_gemm_kernel<1,0><<<dim3(2, mtiles), blk, 2*STG>>>(
        pHh, pHl, pWth + OW_L1, pWtl + OW_L1, bl1,
        pS, nf, EMB, nb, nb, 0, nb, nb, 0, n, HID, EMB);

    // ---- final sigmoid head + s_ci writeout ----
    final_kernel<<<(n * 32 + 255) / 256, blk>>>(Wl2, bl2, n);
    sci_writeout_kernel<<<(n + 255) / 256, blk>>>(outf, n);
}

// round 9
// speedup vs baseline: 1.0875x; 1.0311x over previous
#include <cuda_runtime.h>
#include <cuda_bf16.h>
#include <math.h>
#include <stdint.h>

// ---------------------------------------------------------------------------
// Problem constants
// ---------------------------------------------------------------------------
#define NN    50000
#define EE    800000
#define EMB   256
#define HID   512
#define DDISC 64
#define DCONT 13
#define CAT   (4*EMB)      // 1024
#define SLOPE 0.01f

// transposed-weight pool offsets ([N,K] row-major, bf16)
#define OW_DG  0            // combined [512,64]: rows 0-255 Wd, 256-511 Wg0
#define OW_G1  32768        // [256,256]
#define OW_G2  98304        // [256,256]
#define OW_F   163840       // [512,1024]
#define OW_L1  688128       // [256,512]
#define OW_TOT 819200

// ---------------------------------------------------------------------------
// Scratch — __device__ globals (no cudaMalloc allowed)
// ---------------------------------------------------------------------------
__device__ float g_Y [(long)NN*EMB];     // conv pre-aggregation (fp32)
__device__ float g_S [(long)NN*EMB];     // s
__device__ float g_sci[NN];
__device__ float g_dinv[NN];
__device__ float g_b2[2*EMB];            // concat(bd, bg0)
__device__ int   g_cnt[NN];
__device__ int   g_rowptr[NN+1];
__device__ int   g_cursor[NN];
__device__ int   g_colsrc[EE];
__device__ int   g_is64;

// bf16 split buffers (hi/lo)
__device__ __align__(16) __nv_bfloat16 g_Ah[(long)NN*CAT];   // concat split
__device__ __align__(16) __nv_bfloat16 g_Al[(long)NN*CAT];
__device__ __align__(16) __nv_bfloat16 g_Gh[(long)NN*EMB];   // gcn activation split
__device__ __align__(16) __nv_bfloat16 g_Gl[(long)NN*EMB];
__device__ __align__(16) __nv_bfloat16 g_Hh[(long)NN*HID];   // h_ci split
__device__ __align__(16) __nv_bfloat16 g_Hl[(long)NN*HID];
__device__ __align__(16) __nv_bfloat16 g_Dh[(long)NN*DDISC]; // discrete_x split
__device__ __align__(16) __nv_bfloat16 g_Dl[(long)NN*DDISC];
__device__ __align__(16) __nv_bfloat16 g_Wth[OW_TOT];        // transposed weight pool
__device__ __align__(16) __nv_bfloat16 g_Wtl[OW_TOT];

// ---------------------------------------------------------------------------
// asm helpers (base ISA only — must compile for compute_103)
// ---------------------------------------------------------------------------
__device__ __forceinline__ uint32_t smem_u32(const void* p) {
    uint32_t a;
    asm("{ .reg .u64 t; cvta.to.shared.u64 t, %1; cvt.u32.u64 %0, t; }" : "=r"(a) : "l"(p));
    return a;
}
__device__ __forceinline__ void ldsm4(uint32_t& r0, uint32_t& r1, uint32_t& r2, uint32_t& r3,
                                      uint32_t addr) {
    asm volatile("ldmatrix.sync.aligned.m8n8.x4.shared.b16 {%0,%1,%2,%3}, [%4];"
                 : "=r"(r0), "=r"(r1), "=r"(r2), "=r"(r3) : "r"(addr));
}
__device__ __forceinline__ void mma16816(float* c, const uint32_t* a, const uint32_t* b) {
    asm volatile(
        "mma.sync.aligned.m16n8k16.row.col.f32.bf16.bf16.f32 "
        "{%0,%1,%2,%3}, {%4,%5,%6,%7}, {%8,%9}, {%0,%1,%2,%3};"
        : "+f"(c[0]), "+f"(c[1]), "+f"(c[2]), "+f"(c[3])
        : "r"(a[0]), "r"(a[1]), "r"(a[2]), "r"(a[3]), "r"(b[0]), "r"(b[1]));
}
__device__ __forceinline__ void cp16(uint32_t dst, const void* src, int sz) {
    asm volatile("cp.async.cg.shared.global [%0], [%1], 16, %2;"
                 :: "r"(dst), "l"(src), "r"(sz) : "memory");
}
__device__ __forceinline__ void cp_commit() {
    asm volatile("cp.async.commit_group;" ::: "memory");
}
__device__ __forceinline__ void cp_wait1() {
    asm volatile("cp.async.wait_group 1;" ::: "memory");
}
__device__ __forceinline__ void cp_wait0() {
    asm volatile("cp.async.wait_group 0;" ::: "memory");
}
// byte offset inside a [rows][32 halfs] tile (row stride 64B, 16B-chunk swizzle)
__device__ __forceinline__ uint32_t swa(int r, int ci) {
    return (uint32_t)(r * 64 + ((ci ^ (r & 3) ^ ((r >> 2) & 1)) * 16));
}
__device__ __forceinline__ void split_store(__nv_bfloat16* H, __nv_bfloat16* L,
                                            size_t off, float v0, float v1) {
    __nv_bfloat16 h0 = __float2bfloat16(v0);
    __nv_bfloat16 h1 = __float2bfloat16(v1);
    __nv_bfloat16 l0 = __float2bfloat16(v0 - __bfloat162float(h0));
    __nv_bfloat16 l1 = __float2bfloat16(v1 - __bfloat162float(h1));
    *(__nv_bfloat162*)(H + off) = __nv_bfloat162(h0, h1);
    *(__nv_bfloat162*)(L + off) = __nv_bfloat162(l0, l1);
}

// ---------------------------------------------------------------------------
// bf16x3 HMMA GEMM, cp.async double-buffered, warp tile 64x64 (4 warps).
// C = act(A @ W + bias). A split [M,K] row-major; W split transposed [N,K].
// CTA tile 128x128, 128 threads, K-chunk 32, K%32==0, N%128==0.
// Warp tile 64x64: B fragments reused across 4 m-atoms (halves B smem traffic).
// MODE 0: write Cf fp32.
// MODE 2: write split (Ch,Cl) + fp32 into Cf AND Cf2.
// MODE 3: dual split dest — cols < 256 -> (Ch,Cl,lds); cols >= 256 -> (Ch2,Cl2,lds2).
// Dynamic smem: 2 stages x 32KB = 64KB.
// ---------------------------------------------------------------------------
#define STG 32768
template<int ACT, int MODE>
__global__ __launch_bounds__(128, 2)
void mma_gemm_kernel(const __nv_bfloat16* __restrict__ Ah,
                     const __nv_bfloat16* __restrict__ Al,
                     const __nv_bfloat16* __restrict__ Bh,   // [N,K]
                     const __nv_bfloat16* __restrict__ Bl,
                     const float* __restrict__ bias,
                     float* __restrict__ Cf, float* __restrict__ Cf2, int ldf,
                     __nv_bfloat16* __restrict__ Ch, __nv_bfloat16* __restrict__ Cl, int lds,
                     __nv_bfloat16* __restrict__ Ch2, __nv_bfloat16* __restrict__ Cl2, int lds2,
                     int M, int K, int N)
{
    extern __shared__ char sm[];
    const uint32_t sb = smem_u32(sm);
    const uint32_t oAH = 0, oAL = 8192, oBH = 16384, oBL = 24576;

    int tid = threadIdx.x;
    int wid = tid >> 5;
    int lane = tid & 31;
    int wm = wid & 1;              // 2 warp-rows of 64
    int wn = wid >> 1;             // 2 warp-cols of 64
    int row0 = blockIdx.y * 128;
    int col0 = blockIdx.x * 128;

    float acc[4][8][4];            // 4 m16-atoms x 8 n8-atoms x 4
    #pragma unroll
    for (int i = 0; i < 4; i++)
        #pragma unroll
        for (int j = 0; j < 8; j++)
            #pragma unroll
            for (int q = 0; q < 4; q++) acc[i][j][q] = 0.f;

    int Lg = lane >> 3;
    int Lr = lane & 7;
    const int nchunks = K >> 5;

    auto prefetch = [&](int ch, int stage) {
        int k0 = ch << 5;
        uint32_t base = sb + stage * STG;
        #pragma unroll
        for (int it = 0; it < 4; it++) {
            int idx = tid + it * 128;          // 0..511
            int r = idx >> 2, ci = idx & 3;
            uint32_t sw = swa(r, ci);
            int gr = row0 + r;
            int ok = (gr < M) ? 16 : 0;
            size_t ga = (size_t)(ok ? gr : 0) * K + k0 + ci * 8;
            cp16(base + oAH + sw, Ah + ga, ok);
            cp16(base + oAL + sw, Al + ga, ok);
            size_t gb = (size_t)(col0 + r) * K + k0 + ci * 8;
            cp16(base + oBH + sw, Bh + gb, 16);
            cp16(base + oBL + sw, Bl + gb, 16);
        }
        cp_commit();
    };

    prefetch(0, 0);
    for (int ch = 0; ch < nchunks; ch++) {
        if (ch + 1 < nchunks) {
            prefetch(ch + 1, (ch + 1) & 1);
            cp_wait1();
        } else {
            cp_wait0();
        }
        __syncthreads();
        uint32_t base = sb + (ch & 1) * STG;

        #pragma unroll
        for (int ks = 0; ks < 2; ks++) {
            uint32_t ah[4][4], al[4][4];
            #pragma unroll
            for (int ma = 0; ma < 4; ma++) {
                int ar = wm * 64 + ma * 16 + Lr + (Lg & 1) * 8;
                int ac = ks * 2 + (Lg >> 1);
                uint32_t sw = swa(ar, ac);
                ldsm4(ah[ma][0], ah[ma][1], ah[ma][2], ah[ma][3], base + oAH + sw);
                ldsm4(al[ma][0], al[ma][1], al[ma][2], al[ma][3], base + oAL + sw);
            }
            #pragma unroll
            for (int g = 0; g < 4; g++) {
                int br = wn * 64 + g * 16 + Lr + (Lg >> 1) * 8;
                int bc = ks * 2 + (Lg & 1);
                uint32_t sw = swa(br, bc);
                uint32_t bh[4], bl[4];
                ldsm4(bh[0], bh[1], bh[2], bh[3], base + oBH + sw);
                ldsm4(bl[0], bl[1], bl[2], bl[3], base + oBL + sw);
                #pragma unroll
                for (int ma = 0; ma < 4; ma++) {
                    mma16816(acc[ma][g*2+0], ah[ma], bh + 0);
                    mma16816(acc[ma][g*2+1], ah[ma], bh + 2);
                    mma16816(acc[ma][g*2+0], ah[ma], bl + 0);
                    mma16816(acc[ma][g*2+1], ah[ma], bl + 2);
                    mma16816(acc[ma][g*2+0], al[ma], bh + 0);
                    mma16816(acc[ma][g*2+1], al[ma], bh + 2);
                }
            }
        }
        __syncthreads();
    }

    // ---- epilogue ----
    int rbase = row0 + wm * 64 + (lane >> 2);
    int cbase = col0 + wn * 64 + (lane & 3) * 2;
    #pragma unroll
    for (int ma = 0; ma < 4; ma++) {
        #pragma unroll
        for (int na = 0; na < 8; na++) {
            int gc = cbase + na * 8;
            float b0 = bias ? bias[gc] : 0.f;
            float b1 = bias ? bias[gc + 1] : 0.f;
            #pragma unroll
            for (int h = 0; h < 2; h++) {
                int gr = rbase + ma * 16 + h * 8;
                if (gr < M) {
                    float v0 = acc[ma][na][h * 2 + 0] + b0;
                    float v1 = acc[ma][na][h * 2 + 1] + b1;
                    if (ACT == 1) {
                        v0 = v0 > 0.f ? v0 : SLOPE * v0;
                        v1 = v1 > 0.f ? v1 : SLOPE * v1;
                    }
                    if (MODE == 0 || MODE == 2) {
                        *(float2*)(Cf + (size_t)gr * ldf + gc) = make_float2(v0, v1);
                        if (MODE == 2)
                            *(float2*)(Cf2 + (size_t)gr * ldf + gc) = make_float2(v0, v1);
                    }
                    if (MODE == 2)
                        split_store(Ch, Cl, (size_t)gr * lds + gc, v0, v1);
                    if (MODE == 3) {
                        if (gc < 256)
                            split_store(Ch, Cl, (size_t)gr * lds + gc, v0, v1);
                        else
                            split_store(Ch2, Cl2, (size_t)gr * lds2 + (gc - 256), v0, v1);
                    }
                }
            }
        }
    }
}

// ---------------------------------------------------------------------------
// input feature split (fp32 -> bf16 hi/lo)
// ---------------------------------------------------------------------------
__global__ void splitA_kernel(const float* __restrict__ X,
                              __nv_bfloat16* __restrict__ H,
                              __nv_bfloat16* __restrict__ L, long n)
{
    long i = (long)blockIdx.x * blockDim.x + threadIdx.x;
    if (i >= n) return;
    float a = X[i];
    __nv_bfloat16 h = __float2bfloat16(a);
    H[i] = h;
    L[i] = __float2bfloat16(a - __bfloat162float(h));
}

// ---------------------------------------------------------------------------
// ONE kernel: transpose+split ALL weights into the pool, plus bias concat.
// ---------------------------------------------------------------------------
__global__ void splitW_all_kernel(const float* __restrict__ Wd,  const float* __restrict__ Wg0,
                                  const float* __restrict__ Wg1, const float* __restrict__ Wg2,
                                  const float* __restrict__ Wf,  const float* __restrict__ Wl1,
                                  const float* __restrict__ bd,  const float* __restrict__ bg0)
{
    const int c0 = DDISC*EMB;            // 16384
    const int c1 = c0 + DDISC*EMB;       // 32768
    const int c2 = c1 + EMB*EMB;         // 98304
    const int c3 = c2 + EMB*EMB;         // 163840
    const int c4 = c3 + CAT*HID;         // 688128
    const int c5 = c4 + HID*EMB;         // 819200
    for (long i = (long)blockIdx.x * blockDim.x + threadIdx.x;
         i < c5 + 2*EMB; i += (long)gridDim.x * blockDim.x) {
        if (i >= c5) {                   // bias concat tail
            int j = (int)(i - c5);
            g_b2[j] = (j < EMB) ? bd[j] : bg0[j - EMB];
            continue;
        }
        const float* W; long loc, off; int K, N;
        if (i < c0)      { W = Wd;  loc = i;      off = OW_DG;           K = DDISC; N = EMB; }
        else if (i < c1) { W = Wg0; loc = i - c0; off = OW_DG + (long)EMB*DDISC; K = DDISC; N = EMB; }
        else if (i < c2) { W = Wg1; loc = i - c1; off = OW_G1; K = EMB; N = EMB; }
        else if (i < c3) { W = Wg2; loc = i - c2; off = OW_G2; K = EMB; N = EMB; }
        else if (i < c4) { W = Wf;  loc = i - c3; off = OW_F;  K = CAT; N = HID; }
        else             { W = Wl1; loc = i - c4; off = OW_L1; K = HID; N = EMB; }
        int k = (int)(loc / N), nn = (int)(loc % N);
        float a = W[loc];
        __nv_bfloat16 h = __float2bfloat16(a);
        long o = off + (long)nn * K + k;
        g_Wth[o] = h;
        g_Wtl[o] = __float2bfloat16(a - __bfloat162float(h));
    }
}

// ---------------------------------------------------------------------------
// Edge dtype probe + graph preprocessing
// ---------------------------------------------------------------------------
__global__ void probe_kernel(const int* __restrict__ ei32, int nwords)
{
    __shared__ int nz;
    if (threadIdx.x == 0) nz = 0;
    __syncthreads();
    int lim = nwords < 4096 ? nwords : 4096;
    for (int i = 1 + 2 * threadIdx.x; i < lim; i += 2 * blockDim.x)
        if (ei32[i] != 0) atomicAdd(&nz, 1);
    __syncthreads();
    if (threadIdx.x == 0) g_is64 = (nz == 0) ? 1 : 0;
}

__device__ __forceinline__ int edge_at(const void* base, long i, int is64)
{
    return is64 ? (int)((const long long*)base)[i] : ((const int*)base)[i];
}

__global__ void zero_cnt_kernel(int n) {
    int i = blockIdx.x * blockDim.x + threadIdx.x;
    if (i < n) g_cnt[i] = 0;
}

__global__ void count_kernel(const void* __restrict__ ei, int e, int n) {
    int i = blockIdx.x * blockDim.x + threadIdx.x;
    if (i >= e) return;
    int is64 = g_is64;
    int d = edge_at(ei, (long)e + i, is64);
    if ((unsigned)d < (unsigned)n) atomicAdd(&g_cnt[d], 1);
}

__global__ void dinv_kernel(int n) {
    int i = blockIdx.x * blockDim.x + threadIdx.x;
    if (i < n) g_dinv[i] = rsqrtf((float)(g_cnt[i] + 1));
}

// fast single-block scan: serial per-thread segments + one 1024-wide scan
__global__ void scan_kernel(int n) {
    __shared__ int part[1024];
    int tid = threadIdx.x;
    int per = (n + 1023) >> 10;
    int beg = tid * per;
    int end = beg + per < n ? beg + per : n;
    int s = 0;
    for (int i = beg; i < end; i++) s += g_cnt[i];
    part[tid] = s;
    __syncthreads();
    for (int off = 1; off < 1024; off <<= 1) {
        int t = (tid >= off) ? part[tid - off] : 0;
        __syncthreads();
        part[tid] += t;
        __syncthreads();
    }
    int run = part[tid] - s;
    for (int i = beg; i < end; i++) {
        int v = g_cnt[i];
        g_rowptr[i] = run;
        g_cursor[i] = run;
        run += v;
    }
    if (tid == 1023) g_rowptr[n] = run;
}

__global__ void fill_kernel(const void* __restrict__ ei, int e, int n) {
    int i = blockIdx.x * blockDim.x + threadIdx.x;
    if (i >= e) return;
    int is64 = g_is64;
    int s = edge_at(ei, i, is64);
    int d = edge_at(ei, (long)e + i, is64);
    if ((unsigned)d < (unsigned)n && (unsigned)s < (unsigned)n) {
        int pos = atomicAdd(&g_cursor[d], 1);
        if (pos < EE) g_colsrc[pos] = s;
    }
}

// ---------------------------------------------------------------------------
// Merged continuous embeds (K=13), one launch: half = blockIdx.x>>1.
// ---------------------------------------------------------------------------
__global__ __launch_bounds__(256)
void cont_embed_kernel(const float* __restrict__ X,   // continous_x [M, 39]
                       const float* __restrict__ Wc1, const float* __restrict__ bc1,
                       const float* __restrict__ Wc2, const float* __restrict__ bc2,
                       __nv_bfloat16* __restrict__ Ch, __nv_bfloat16* __restrict__ Cl,
                       int M)
{
    const int K = DCONT, NC = EMB, lda = 3*DCONT;
    int half = blockIdx.x >> 1;
    int col0 = (blockIdx.x & 1) * 128;
    const float* A = X + half * DCONT;
    const float* W = half ? Wc2 : Wc1;
    const float* bias = half ? bc2 : bc1;
    __nv_bfloat16* OH = Ch + (1 + half) * EMB;
    __nv_bfloat16* OL = Cl + (1 + half) * EMB;

    __shared__ float As[16][128];
    __shared__ float Ws[16][128];

    int tid = threadIdx.x;
    int tx = tid & 15;
    int ty = tid >> 4;
    int row0 = blockIdx.y * 128;

    float acc[8][8];
    #pragma unroll
    for (int i = 0; i < 8; i++)
        #pragma unroll
        for (int j = 0; j < 8; j++) acc[i][j] = 0.f;

    {
        int a_row = tid >> 1;
        int a_col = (tid & 1) * 8;
        #pragma unroll
        for (int j = 0; j < 8; j++) {
            int r = row0 + a_row, c = a_col + j;
            As[a_col + j][a_row] = (r < M && c < K) ? A[(long)r * lda + c] : 0.f;
        }
        int w_k = tid >> 5;
        int w_n = (tid & 31) * 4;
        #pragma unroll
        for (int rep = 0; rep < 2; rep++) {
            int kk = w_k + rep * 8;
            #pragma unroll
            for (int j = 0; j < 4; j++) {
                int nn = col0 + w_n + j;
                Ws[kk][w_n + j] = (kk < K) ? W[(long)kk * NC + nn] : 0.f;
            }
        }
    }
    __syncthreads();
    #pragma unroll
    for (int k = 0; k < 13; k++) {
        float a[8], b[8];
        #pragma unroll
        for (int i = 0; i < 8; i++) a[i] = As[k][ty * 8 + i];
        #pragma unroll
        for (int j = 0; j < 8; j++) b[j] = Ws[k][tx * 8 + j];
        #pragma unroll
        for (int i = 0; i < 8; i++)
            #pragma unroll
            for (int j = 0; j < 8; j++)
                acc[i][j] += a[i] * b[j];
    }

    #pragma unroll
    for (int i = 0; i < 8; i++) {
        int r = row0 + ty * 8 + i;
        if (r >= M) continue;
        #pragma unroll
        for (int j = 0; j < 8; j += 2) {
            int c = col0 + tx * 8 + j;
            float v0 = acc[i][j] + bias[c];
            float v1 = acc[i][j + 1] + bias[c + 1];
            v0 = v0 > 0.f ? v0 : SLOPE * v0;
            v1 = v1 > 0.f ? v1 : SLOPE * v1;
            split_store(OH, OL, (size_t)r * CAT + c, v0, v1);
        }
    }
}

// ---------------------------------------------------------------------------
// GCN aggregation (one warp per node), float4 gathers, writes bf16 split.
// ---------------------------------------------------------------------------
__global__ __launch_bounds__(256)
void agg_kernel(const float* __restrict__ Y, const float* __restrict__ bias,
                __nv_bfloat16* __restrict__ Oh, __nv_bfloat16* __restrict__ Ol,
                int ldc, int n)
{
    int warp = (blockIdx.x * blockDim.x + threadIdx.x) >> 5;
    int lane = threadIdx.x & 31;
    if (warp >= n) return;
    int beg = g_rowptr[warp], end = g_rowptr[warp + 1];
    int c0 = lane * 8;
    float4 a0 = make_float4(0.f, 0.f, 0.f, 0.f);
    float4 a1 = make_float4(0.f, 0.f, 0.f, 0.f);
    for (int e = beg; e < end; e++) {
        int s = g_colsrc[e];
        float w = g_dinv[s];
        const float4* yr = (const float4*)(Y + (size_t)s * EMB + c0);
        float4 y0 = yr[0], y1 = yr[1];
        a0.x += y0.x * w; a0.y += y0.y * w; a0.z += y0.z * w; a0.w += y0.w * w;
        a1.x += y1.x * w; a1.y += y1.y * w; a1.z += y1.z * w; a1.w += y1.w * w;
    }
    float di = g_dinv[warp];
    float dii = di * di;
    const float4* ys = (const float4*)(Y + (size_t)warp * EMB + c0);
    float4 s0 = ys[0], s1 = ys[1];
    const float4* bp = (const float4*)(bias + c0);
    float4 b0 = bp[0], b1 = bp[1];
    float v[8];
    v[0] = di * a0.x + dii * s0.x + b0.x;
    v[1] = di * a0.y + dii * s0.y + b0.y;
    v[2] = di * a0.z + dii * s0.z + b0.z;
    v[3] = di * a0.w + dii * s0.w + b0.w;
    v[4] = di * a1.x + dii * s1.x + b1.x;
    v[5] = di * a1.y + dii * s1.y + b1.y;
    v[6] = di * a1.z + dii * s1.z + b1.z;
    v[7] = di * a1.w + dii * s1.w + b1.w;
    size_t ob = (size_t)warp * ldc + c0;
    #pragma unroll
    for (int j = 0; j < 8; j += 2) {
        float v0 = v[j] > 0.f ? v[j] : SLOPE * v[j];
        float v1 = v[j+1] > 0.f ? v[j+1] : SLOPE * v[j+1];
        split_store(Oh, Ol, ob + j, v0, v1);
    }
}

// ---------------------------------------------------------------------------
// Final sigmoid head + small s_ci writeout
// ---------------------------------------------------------------------------
__global__ __launch_bounds__(256)
void final_kernel(const float* __restrict__ Wl2, const float* __restrict__ bl2, int n)
{
    int warp = (blockIdx.x * blockDim.x + threadIdx.x) >> 5;
    int lane = threadIdx.x & 31;
    if (warp >= n) return;
    const float* sr = g_S + (long)warp * EMB;
    float a = 0.f;
    #pragma unroll
    for (int j = 0; j < 8; j++) {
        int c = lane + 32 * j;
        a += sr[c] * Wl2[c];
    }
    #pragma unroll
    for (int off = 16; off > 0; off >>= 1)
        a += __shfl_xor_sync(0xffffffffu, a, off);
    if (lane == 0)
        g_sci[warp] = 1.f / (1.f + expf(-(a + bl2[0])));
}

__global__ void sci_writeout_kernel(float* __restrict__ out, int n)
{
    int i = blockIdx.x * blockDim.x + threadIdx.x;
    if (i < n) {
        float v = g_sci[i];
        out[i] = v;
        out[n + i] = v;
        out[2L * n + i] = v;
    }
}

// ---------------------------------------------------------------------------
// Launch
// ---------------------------------------------------------------------------
extern "C" void kernel_launch(void* const* d_in, const int* in_sizes, int n_in,
                              void* d_out, int out_size)
{
    const float* discrete_x = (const float*)d_in[0];
    const float* continous_x = (const float*)d_in[1];
    const float* Wd  = (const float*)d_in[2];
    const float* bd  = (const float*)d_in[3];
    const float* Wc1 = (const float*)d_in[4];
    const float* bc1 = (const float*)d_in[5];
    const float* Wc2 = (const float*)d_in[6];
    const float* bc2 = (const float*)d_in[7];
    const float* Wg0 = (const float*)d_in[8];
    const float* bg0 = (const float*)d_in[9];
    const float* Wg1 = (const float*)d_in[10];
    const float* bg1 = (const float*)d_in[11];
    const float* Wg2 = (const float*)d_in[12];
    const float* bg2 = (const float*)d_in[13];
    const float* Wf  = (const float*)d_in[14];
    const float* bf  = (const float*)d_in[15];
    const float* Wl1 = (const float*)d_in[16];
    const float* bl1 = (const float*)d_in[17];
    const float* Wl2 = (const float*)d_in[18];
    const float* bl2 = (const float*)d_in[19];
    const void*  edge_index = d_in[20];

    const int n = in_sizes[0] / DDISC;       // 50000
    const int e = in_sizes[20] / 2;          // 800000

    float *pY, *pS, *pB2;
    cudaGetSymbolAddress((void**)&pY, g_Y);
    cudaGetSymbolAddress((void**)&pS, g_S);
    cudaGetSymbolAddress((void**)&pB2, g_b2);
    __nv_bfloat16 *pAh, *pAl, *pGh, *pGl, *pHh, *pHl, *pDh, *pDl, *pWth, *pWtl;
    cudaGetSymbolAddress((void**)&pAh, g_Ah);
    cudaGetSymbolAddress((void**)&pAl, g_Al);
    cudaGetSymbolAddress((void**)&pGh, g_Gh);
    cudaGetSymbolAddress((void**)&pGl, g_Gl);
    cudaGetSymbolAddress((void**)&pHh, g_Hh);
    cudaGetSymbolAddress((void**)&pHl, g_Hl);
    cudaGetSymbolAddress((void**)&pDh, g_Dh);
    cudaGetSymbolAddress((void**)&pDl, g_Dl);
    cudaGetSymbolAddress((void**)&pWth, g_Wth);
    cudaGetSymbolAddress((void**)&pWtl, g_Wtl);

    cudaFuncSetAttribute(mma_gemm_kernel<0,0>, cudaFuncAttributeMaxDynamicSharedMemorySize, 2*STG);
    cudaFuncSetAttribute(mma_gemm_kernel<1,0>, cudaFuncAttributeMaxDynamicSharedMemorySize, 2*STG);
    cudaFuncSetAttribute(mma_gemm_kernel<1,2>, cudaFuncAttributeMaxDynamicSharedMemorySize, 2*STG);
    cudaFuncSetAttribute(mma_gemm_kernel<1,3>, cudaFuncAttributeMaxDynamicSharedMemorySize, 2*STG);

    dim3 blk(256);
    dim3 gblk(128);
    const int mtiles = (n + 127) / 128;   // 391
    float* outf = (float*)d_out;
    long tot = (long)n * HID;
    __nv_bfloat16* nb = nullptr;
    float* nf = nullptr;

    // Order arranged so ncu's "-s 5 -c 1" window (6th launch) captures the
    // GCN conv-1 GEMM (K=256) instead of a trivial elementwise kernel.
    splitW_all_kernel<<<592, blk>>>(Wd, Wg0, Wg1, Wg2, Wf, Wl1, bd, bg0);          // 1
    {
        long nd = (long)n * DDISC;
        splitA_kernel<<<(unsigned)((nd + 255) / 256), blk>>>(discrete_x, pDh, pDl, nd); // 2
    }
    mma_gemm_kernel<1,3><<<dim3(4, mtiles), gblk, 2*STG>>>(                        // 3
        pDh, pDl, pWth + OW_DG, pWtl + OW_DG, pB2,
        nf, nf, 0, pAh, pAl, CAT, pGh, pGl, EMB, n, DDISC, 512);
    probe_kernel<<<1, 256>>>((const int*)edge_index, 2 * e);                        // 4
    zero_cnt_kernel<<<(n + 255) / 256, blk>>>(n);                                   // 5
    mma_gemm_kernel<0,0><<<dim3(2, mtiles), gblk, 2*STG>>>(                        // 6 (profiled)
        pGh, pGl, pWth + OW_G1, pWtl + OW_G1, nf,
        pY, nf, EMB, nb, nb, 0, nb, nb, 0, n, EMB, EMB);
    count_kernel<<<(e + 255) / 256, blk>>>(edge_index, e, n);                       // 7
    dinv_kernel<<<(n + 255) / 256, blk>>>(n);                                       // 8
    scan_kernel<<<1, 1024>>>(n);                                                    // 9
    fill_kernel<<<(e + 255) / 256, blk>>>(edge_index, e, n);                        // 10
    cont_embed_kernel<<<dim3(4, mtiles), blk>>>(continous_x, Wc1, bc1, Wc2, bc2,    // 11
                                                pAh, pAl, n);

    // ---- GCN conv 1 aggregation ----
    agg_kernel<<<(n * 32 + 255) / 256, blk>>>(pY, bg1, pGh, pGl, EMB, n);

    // ---- GCN conv 2 ----
    mma_gemm_kernel<0,0><<<dim3(2, mtiles), gblk, 2*STG>>>(
        pGh, pGl, pWth + OW_G2, pWtl + OW_G2, nf,
        pY, nf, EMB, nb, nb, 0, nb, nb, 0, n, EMB, EMB);
    agg_kernel<<<(n * 32 + 255) / 256, blk>>>(pY, bg2, pAh + 3*EMB, pAl + 3*EMB, CAT, n);

    // ---- fusion MLP: H -> split + dual fp32 into d_out ----
    mma_gemm_kernel<1,2><<<dim3(4, mtiles), gblk, 2*STG>>>(
        pAh, pAl, pWth + OW_F, pWtl + OW_F, bf,
        outf + 3L * n, outf + 3L * n + tot, HID, pHh, pHl, HID, nb, nb, 0, n, CAT, HID);
    mma_gemm_kernel<1,0><<<dim3(2, mtiles), gblk, 2*STG>>>(
        pHh, pHl, pWth + OW_L1, pWtl + OW_L1, bl1,
        pS, nf, EMB, nb, nb, 0, nb, nb, 0, n, HID, EMB);

    // ---- final sigmoid head + s_ci writeout ----
    final_kernel<<<(n * 32 + 255) / 256, blk>>>(Wl2, bl2, n);
    sci_writeout_kernel<<<(n + 255) / 256, blk>>>(outf, n);
}

// round 10
// speedup vs baseline: 1.1734x; 1.0790x over previous
#include <cuda_runtime.h>
#include <cuda_bf16.h>
#include <math.h>
#include <stdint.h>

// ---------------------------------------------------------------------------
// Problem constants
// ---------------------------------------------------------------------------
#define NN    50000
#define EE    800000
#define EMB   256
#define HID   512
#define DDISC 64
#define DCONT 13
#define CAT   (4*EMB)      // 1024
#define SLOPE 0.01f

// transposed-weight pool offsets ([N,K] row-major, bf16)
#define OW_DG  0            // combined [512,64]: rows 0-255 Wd, 256-511 Wg0
#define OW_G1  32768        // [256,256]
#define OW_G2  98304        // [256,256]
#define OW_F   163840       // [512,1024]
#define OW_L1  688128       // [256,512]
#define OW_TOT 819200

// ---------------------------------------------------------------------------
// Scratch — __device__ globals (no cudaMalloc allowed)
// ---------------------------------------------------------------------------
__device__ float g_Y [(long)NN*EMB];     // conv pre-aggregation (fp32)
__device__ float g_S [(long)NN*EMB];     // s
__device__ float g_sci[NN];
__device__ float g_dinv[NN];
__device__ float g_b2[2*EMB];            // concat(bd, bg0)
__device__ int   g_cnt[NN];
__device__ int   g_rowptr[NN+1];
__device__ int   g_cursor[NN];
__device__ int   g_colsrc[EE];
__device__ int   g_is64;

// bf16 split buffers (hi/lo)
__device__ __align__(16) __nv_bfloat16 g_Ah[(long)NN*CAT];   // concat split
__device__ __align__(16) __nv_bfloat16 g_Al[(long)NN*CAT];
__device__ __align__(16) __nv_bfloat16 g_Gh[(long)NN*EMB];   // gcn activation split
__device__ __align__(16) __nv_bfloat16 g_Gl[(long)NN*EMB];
__device__ __align__(16) __nv_bfloat16 g_Hh[(long)NN*HID];   // h_ci split
__device__ __align__(16) __nv_bfloat16 g_Hl[(long)NN*HID];
__device__ __align__(16) __nv_bfloat16 g_Dh[(long)NN*DDISC]; // discrete_x split
__device__ __align__(16) __nv_bfloat16 g_Dl[(long)NN*DDISC];
__device__ __align__(16) __nv_bfloat16 g_Wth[OW_TOT];        // transposed weight pool
__device__ __align__(16) __nv_bfloat16 g_Wtl[OW_TOT];

// ---------------------------------------------------------------------------
// asm helpers (base ISA only — must compile for compute_103)
// ---------------------------------------------------------------------------
__device__ __forceinline__ uint32_t smem_u32(const void* p) {
    uint32_t a;
    asm("{ .reg .u64 t; cvta.to.shared.u64 t, %1; cvt.u32.u64 %0, t; }" : "=r"(a) : "l"(p));
    return a;
}
__device__ __forceinline__ void ldsm4(uint32_t& r0, uint32_t& r1, uint32_t& r2, uint32_t& r3,
                                      uint32_t addr) {
    asm volatile("ldmatrix.sync.aligned.m8n8.x4.shared.b16 {%0,%1,%2,%3}, [%4];"
                 : "=r"(r0), "=r"(r1), "=r"(r2), "=r"(r3) : "r"(addr));
}
__device__ __forceinline__ void mma16816(float* c, const uint32_t* a, const uint32_t* b) {
    asm volatile(
        "mma.sync.aligned.m16n8k16.row.col.f32.bf16.bf16.f32 "
        "{%0,%1,%2,%3}, {%4,%5,%6,%7}, {%8,%9}, {%0,%1,%2,%3};"
        : "+f"(c[0]), "+f"(c[1]), "+f"(c[2]), "+f"(c[3])
        : "r"(a[0]), "r"(a[1]), "r"(a[2]), "r"(a[3]), "r"(b[0]), "r"(b[1]));
}
__device__ __forceinline__ void cp16(uint32_t dst, const void* src, int sz) {
    asm volatile("cp.async.cg.shared.global [%0], [%1], 16, %2;"
                 :: "r"(dst), "l"(src), "r"(sz) : "memory");
}
__device__ __forceinline__ void cp_commit() {
    asm volatile("cp.async.commit_group;" ::: "memory");
}
__device__ __forceinline__ void cp_wait1() {
    asm volatile("cp.async.wait_group 1;" ::: "memory");
}
__device__ __forceinline__ void cp_wait0() {
    asm volatile("cp.async.wait_group 0;" ::: "memory");
}
// byte offset inside a [rows][32 halfs] tile (row stride 64B, 16B-chunk swizzle)
__device__ __forceinline__ uint32_t swa(int r, int ci) {
    return (uint32_t)(r * 64 + ((ci ^ (r & 3) ^ ((r >> 2) & 1)) * 16));
}
__device__ __forceinline__ void split_store(__nv_bfloat16* H, __nv_bfloat16* L,
                                            size_t off, float v0, float v1) {
    __nv_bfloat16 h0 = __float2bfloat16(v0);
    __nv_bfloat16 h1 = __float2bfloat16(v1);
    __nv_bfloat16 l0 = __float2bfloat16(v0 - __bfloat162float(h0));
    __nv_bfloat16 l1 = __float2bfloat16(v1 - __bfloat162float(h1));
    *(__nv_bfloat162*)(H + off) = __nv_bfloat162(h0, h1);
    *(__nv_bfloat162*)(L + off) = __nv_bfloat162(l0, l1);
}

// ---------------------------------------------------------------------------
// bf16x3 HMMA GEMM, cp.async double-buffered, warp tile 64x64 (4 warps).
// CTA tile 128x128, 128 threads, K-chunk 32, K%32==0, N%128==0.
// MODE 0: write Cf fp32.
// MODE 2: write split (Ch,Cl) + fp32 into Cf AND Cf2.
// MODE 3: dual split dest — cols < 256 -> (Ch,Cl,lds); cols >= 256 -> (Ch2,Cl2,lds2).
// Dynamic smem: 2 stages x 32KB = 64KB.
// ---------------------------------------------------------------------------
#define STG 32768
template<int ACT, int MODE>
__global__ __launch_bounds__(128, 2)
void mma_gemm_kernel(const __nv_bfloat16* __restrict__ Ah,
                     const __nv_bfloat16* __restrict__ Al,
                     const __nv_bfloat16* __restrict__ Bh,   // [N,K]
                     const __nv_bfloat16* __restrict__ Bl,
                     const float* __restrict__ bias,
                     float* __restrict__ Cf, float* __restrict__ Cf2, int ldf,
                     __nv_bfloat16* __restrict__ Ch, __nv_bfloat16* __restrict__ Cl, int lds,
                     __nv_bfloat16* __restrict__ Ch2, __nv_bfloat16* __restrict__ Cl2, int lds2,
                     int M, int K, int N)
{
    extern __shared__ char sm[];
    const uint32_t sb = smem_u32(sm);
    const uint32_t oAH = 0, oAL = 8192, oBH = 16384, oBL = 24576;

    int tid = threadIdx.x;
    int wid = tid >> 5;
    int lane = tid & 31;
    int wm = wid & 1;              // 2 warp-rows of 64
    int wn = wid >> 1;             // 2 warp-cols of 64
    int row0 = blockIdx.y * 128;
    int col0 = blockIdx.x * 128;

    float acc[4][8][4];
    #pragma unroll
    for (int i = 0; i < 4; i++)
        #pragma unroll
        for (int j = 0; j < 8; j++)
            #pragma unroll
            for (int q = 0; q < 4; q++) acc[i][j][q] = 0.f;

    int Lg = lane >> 3;
    int Lr = lane & 7;
    const int nchunks = K >> 5;

    auto prefetch = [&](int ch, int stage) {
        int k0 = ch << 5;
        uint32_t base = sb + stage * STG;
        #pragma unroll
        for (int it = 0; it < 4; it++) {
            int idx = tid + it * 128;          // 0..511
            int r = idx >> 2, ci = idx & 3;
            uint32_t sw = swa(r, ci);
            int gr = row0 + r;
            int ok = (gr < M) ? 16 : 0;
            size_t ga = (size_t)(ok ? gr : 0) * K + k0 + ci * 8;
            cp16(base + oAH + sw, Ah + ga, ok);
            cp16(base + oAL + sw, Al + ga, ok);
            size_t gb = (size_t)(col0 + r) * K + k0 + ci * 8;
            cp16(base + oBH + sw, Bh + gb, 16);
            cp16(base + oBL + sw, Bl + gb, 16);
        }
        cp_commit();
    };

    prefetch(0, 0);
    for (int ch = 0; ch < nchunks; ch++) {
        if (ch + 1 < nchunks) {
            prefetch(ch + 1, (ch + 1) & 1);
            cp_wait1();
        } else {
            cp_wait0();
        }
        __syncthreads();
        uint32_t base = sb + (ch & 1) * STG;

        #pragma unroll
        for (int ks = 0; ks < 2; ks++) {
            uint32_t ah[4][4], al[4][4];
            #pragma unroll
            for (int ma = 0; ma < 4; ma++) {
                int ar = wm * 64 + ma * 16 + Lr + (Lg & 1) * 8;
                int ac = ks * 2 + (Lg >> 1);
                uint32_t sw = swa(ar, ac);
                ldsm4(ah[ma][0], ah[ma][1], ah[ma][2], ah[ma][3], base + oAH + sw);
                ldsm4(al[ma][0], al[ma][1], al[ma][2], al[ma][3], base + oAL + sw);
            }
            #pragma unroll
            for (int g = 0; g < 4; g++) {
                int br = wn * 64 + g * 16 + Lr + (Lg >> 1) * 8;
                int bc = ks * 2 + (Lg & 1);
                uint32_t sw = swa(br, bc);
                uint32_t bh[4], bl[4];
                ldsm4(bh[0], bh[1], bh[2], bh[3], base + oBH + sw);
                ldsm4(bl[0], bl[1], bl[2], bl[3], base + oBL + sw);
                #pragma unroll
                for (int ma = 0; ma < 4; ma++) {
                    mma16816(acc[ma][g*2+0], ah[ma], bh + 0);
                    mma16816(acc[ma][g*2+1], ah[ma], bh + 2);
                    mma16816(acc[ma][g*2+0], ah[ma], bl + 0);
                    mma16816(acc[ma][g*2+1], ah[ma], bl + 2);
                    mma16816(acc[ma][g*2+0], al[ma], bh + 0);
                    mma16816(acc[ma][g*2+1], al[ma], bh + 2);
                }
            }
        }
        __syncthreads();
    }

    // ---- epilogue ----
    int rbase = row0 + wm * 64 + (lane >> 2);
    int cbase = col0 + wn * 64 + (lane & 3) * 2;
    #pragma unroll
    for (int ma = 0; ma < 4; ma++) {
        #pragma unroll
        for (int na = 0; na < 8; na++) {
            int gc = cbase + na * 8;
            float b0 = bias ? bias[gc] : 0.f;
            float b1 = bias ? bias[gc + 1] : 0.f;
            #pragma unroll
            for (int h = 0; h < 2; h++) {
                int gr = rbase + ma * 16 + h * 8;
                if (gr < M) {
                    float v0 = acc[ma][na][h * 2 + 0] + b0;
                    float v1 = acc[ma][na][h * 2 + 1] + b1;
                    if (ACT == 1) {
                        v0 = v0 > 0.f ? v0 : SLOPE * v0;
                        v1 = v1 > 0.f ? v1 : SLOPE * v1;
                    }
                    if (MODE == 0 || MODE == 2) {
                        *(float2*)(Cf + (size_t)gr * ldf + gc) = make_float2(v0, v1);
                        if (MODE == 2)
                            *(float2*)(Cf2 + (size_t)gr * ldf + gc) = make_float2(v0, v1);
                    }
                    if (MODE == 2)
                        split_store(Ch, Cl, (size_t)gr * lds + gc, v0, v1);
                    if (MODE == 3) {
                        if (gc < 256)
                            split_store(Ch, Cl, (size_t)gr * lds + gc, v0, v1);
                        else
                            split_store(Ch2, Cl2, (size_t)gr * lds2 + (gc - 256), v0, v1);
                    }
                }
            }
        }
    }
}

// ---------------------------------------------------------------------------
// input feature split (fp32 -> bf16 hi/lo)
// ---------------------------------------------------------------------------
__global__ void splitA_kernel(const float* __restrict__ X,
                              __nv_bfloat16* __restrict__ H,
                              __nv_bfloat16* __restrict__ L, long n)
{
    long i = (long)blockIdx.x * blockDim.x + threadIdx.x;
    if (i >= n) return;
    float a = X[i];
    __nv_bfloat16 h = __float2bfloat16(a);
    H[i] = h;
    L[i] = __float2bfloat16(a - __bfloat162float(h));
}

// ---------------------------------------------------------------------------
// ONE kernel: transpose+split ALL weights into the pool, plus bias concat.
// ---------------------------------------------------------------------------
__global__ void splitW_all_kernel(const float* __restrict__ Wd,  const float* __restrict__ Wg0,
                                  const float* __restrict__ Wg1, const float* __restrict__ Wg2,
                                  const float* __restrict__ Wf,  const float* __restrict__ Wl1,
                                  const float* __restrict__ bd,  const float* __restrict__ bg0)
{
    const int c0 = DDISC*EMB;            // 16384
    const int c1 = c0 + DDISC*EMB;       // 32768
    const int c2 = c1 + EMB*EMB;         // 98304
    const int c3 = c2 + EMB*EMB;         // 163840
    const int c4 = c3 + CAT*HID;         // 688128
    const int c5 = c4 + HID*EMB;         // 819200
    for (long i = (long)blockIdx.x * blockDim.x + threadIdx.x;
         i < c5 + 2*EMB; i += (long)gridDim.x * blockDim.x) {
        if (i >= c5) {                   // bias concat tail
            int j = (int)(i - c5);
            g_b2[j] = (j < EMB) ? bd[j] : bg0[j - EMB];
            continue;
        }
        const float* W; long loc, off; int K, N;
        if (i < c0)      { W = Wd;  loc = i;      off = OW_DG;           K = DDISC; N = EMB; }
        else if (i < c1) { W = Wg0; loc = i - c0; off = OW_DG + (long)EMB*DDISC; K = DDISC; N = EMB; }
        else if (i < c2) { W = Wg1; loc = i - c1; off = OW_G1; K = EMB; N = EMB; }
        else if (i < c3) { W = Wg2; loc = i - c2; off = OW_G2; K = EMB; N = EMB; }
        else if (i < c4) { W = Wf;  loc = i - c3; off = OW_F;  K = CAT; N = HID; }
        else             { W = Wl1; loc = i - c4; off = OW_L1; K = HID; N = EMB; }
        int k = (int)(loc / N), nn = (int)(loc % N);
        float a = W[loc];
        __nv_bfloat16 h = __float2bfloat16(a);
        long o = off + (long)nn * K + k;
        g_Wth[o] = h;
        g_Wtl[o] = __float2bfloat16(a - __bfloat162float(h));
    }
}

// ---------------------------------------------------------------------------
// Edge dtype probe + graph preprocessing
// ---------------------------------------------------------------------------
__global__ void probe_kernel(const int* __restrict__ ei32, int nwords)
{
    __shared__ int nz;
    if (threadIdx.x == 0) nz = 0;
    __syncthreads();
    int lim = nwords < 4096 ? nwords : 4096;
    for (int i = 1 + 2 * threadIdx.x; i < lim; i += 2 * blockDim.x)
        if (ei32[i] != 0) atomicAdd(&nz, 1);
    __syncthreads();
    if (threadIdx.x == 0) g_is64 = (nz == 0) ? 1 : 0;
}

__device__ __forceinline__ int edge_at(const void* base, long i, int is64)
{
    return is64 ? (int)((const long long*)base)[i] : ((const int*)base)[i];
}

__global__ void zero_cnt_kernel(int n) {
    int i = blockIdx.x * blockDim.x + threadIdx.x;
    if (i < n) g_cnt[i] = 0;
}

__global__ void count_kernel(const void* __restrict__ ei, int e, int n) {
    int i = blockIdx.x * blockDim.x + threadIdx.x;
    if (i >= e) return;
    int is64 = g_is64;
    int d = edge_at(ei, (long)e + i, is64);
    if ((unsigned)d < (unsigned)n) atomicAdd(&g_cnt[d], 1);
}

// fast single-block scan (also computes dinv = rsqrt(cnt+1))
__global__ void scan_kernel(int n) {
    __shared__ int part[1024];
    int tid = threadIdx.x;
    int per = (n + 1023) >> 10;
    int beg = tid * per;
    int end = beg + per < n ? beg + per : n;
    int s = 0;
    for (int i = beg; i < end; i++) {
        int v = g_cnt[i];
        s += v;
        g_dinv[i] = rsqrtf((float)(v + 1));
    }
    part[tid] = s;
    __syncthreads();
    for (int off = 1; off < 1024; off <<= 1) {
        int t = (tid >= off) ? part[tid - off] : 0;
        __syncthreads();
        part[tid] += t;
        __syncthreads();
    }
    int run = part[tid] - s;
    for (int i = beg; i < end; i++) {
        int v = g_cnt[i];
        g_rowptr[i] = run;
        g_cursor[i] = run;
        run += v;
    }
    if (tid == 1023) g_rowptr[n] = run;
}

__global__ void fill_kernel(const void* __restrict__ ei, int e, int n) {
    int i = blockIdx.x * blockDim.x + threadIdx.x;
    if (i >= e) return;
    int is64 = g_is64;
    int s = edge_at(ei, i, is64);
    int d = edge_at(ei, (long)e + i, is64);
    if ((unsigned)d < (unsigned)n && (unsigned)s < (unsigned)n) {
        int pos = atomicAdd(&g_cursor[d], 1);
        if (pos < EE) g_colsrc[pos] = s;
    }
}

// ---------------------------------------------------------------------------
// Merged continuous embeds (K=13), one launch: half = blockIdx.x>>1.
// ---------------------------------------------------------------------------
__global__ __launch_bounds__(256)
void cont_embed_kernel(const float* __restrict__ X,   // continous_x [M, 39]
                       const float* __restrict__ Wc1, const float* __restrict__ bc1,
                       const float* __restrict__ Wc2, const float* __restrict__ bc2,
                       __nv_bfloat16* __restrict__ Ch, __nv_bfloat16* __restrict__ Cl,
                       int M)
{
    const int K = DCONT, NC = EMB, lda = 3*DCONT;
    int half = blockIdx.x >> 1;
    int col0 = (blockIdx.x & 1) * 128;
    const float* A = X + half * DCONT;
    const float* W = half ? Wc2 : Wc1;
    const float* bias = half ? bc2 : bc1;
    __nv_bfloat16* OH = Ch + (1 + half) * EMB;
    __nv_bfloat16* OL = Cl + (1 + half) * EMB;

    __shared__ float As[16][128];
    __shared__ float Ws[16][128];

    int tid = threadIdx.x;
    int tx = tid & 15;
    int ty = tid >> 4;
    int row0 = blockIdx.y * 128;

    float acc[8][8];
    #pragma unroll
    for (int i = 0; i < 8; i++)
        #pragma unroll
        for (int j = 0; j < 8; j++) acc[i][j] = 0.f;

    {
        int a_row = tid >> 1;
        int a_col = (tid & 1) * 8;
        #pragma unroll
        for (int j = 0; j < 8; j++) {
            int r = row0 + a_row, c = a_col + j;
            As[a_col + j][a_row] = (r < M && c < K) ? A[(long)r * lda + c] : 0.f;
        }
        int w_k = tid >> 5;
        int w_n = (tid & 31) * 4;
        #pragma unroll
        for (int rep = 0; rep < 2; rep++) {
            int kk = w_k + rep * 8;
            #pragma unroll
            for (int j = 0; j < 4; j++) {
                int nn = col0 + w_n + j;
                Ws[kk][w_n + j] = (kk < K) ? W[(long)kk * NC + nn] : 0.f;
            }
        }
    }
    __syncthreads();
    #pragma unroll
    for (int k = 0; k < 13; k++) {
        float a[8], b[8];
        #pragma unroll
        for (int i = 0; i < 8; i++) a[i] = As[k][ty * 8 + i];
        #pragma unroll
        for (int j = 0; j < 8; j++) b[j] = Ws[k][tx * 8 + j];
        #pragma unroll
        for (int i = 0; i < 8; i++)
            #pragma unroll
            for (int j = 0; j < 8; j++)
                acc[i][j] += a[i] * b[j];
    }

    #pragma unroll
    for (int i = 0; i < 8; i++) {
        int r = row0 + ty * 8 + i;
        if (r >= M) continue;
        #pragma unroll
        for (int j = 0; j < 8; j += 2) {
            int c = col0 + tx * 8 + j;
            float v0 = acc[i][j] + bias[c];
            float v1 = acc[i][j + 1] + bias[c + 1];
            v0 = v0 > 0.f ? v0 : SLOPE * v0;
            v1 = v1 > 0.f ? v1 : SLOPE * v1;
            split_store(OH, OL, (size_t)r * CAT + c, v0, v1);
        }
    }
}

// ---------------------------------------------------------------------------
// GCN aggregation (one warp per node), float4 gathers, writes bf16 split.
// ---------------------------------------------------------------------------
__global__ __launch_bounds__(256)
void agg_kernel(const float* __restrict__ Y, const float* __restrict__ bias,
                __nv_bfloat16* __restrict__ Oh, __nv_bfloat16* __restrict__ Ol,
                int ldc, int n)
{
    int warp = (blockIdx.x * blockDim.x + threadIdx.x) >> 5;
    int lane = threadIdx.x & 31;
    if (warp >= n) return;
    int beg = g_rowptr[warp], end = g_rowptr[warp + 1];
    int c0 = lane * 8;
    float4 a0 = make_float4(0.f, 0.f, 0.f, 0.f);
    float4 a1 = make_float4(0.f, 0.f, 0.f, 0.f);
    for (int e = beg; e < end; e++) {
        int s = g_colsrc[e];
        float w = g_dinv[s];
        const float4* yr = (const float4*)(Y + (size_t)s * EMB + c0);
        float4 y0 = yr[0], y1 = yr[1];
        a0.x += y0.x * w; a0.y += y0.y * w; a0.z += y0.z * w; a0.w += y0.w * w;
        a1.x += y1.x * w; a1.y += y1.y * w; a1.z += y1.z * w; a1.w += y1.w * w;
    }
    float di = g_dinv[warp];
    float dii = di * di;
    const float4* ys = (const float4*)(Y + (size_t)warp * EMB + c0);
    float4 s0 = ys[0], s1 = ys[1];
    const float4* bp = (const float4*)(bias + c0);
    float4 b0 = bp[0], b1 = bp[1];
    float v[8];
    v[0] = di * a0.x + dii * s0.x + b0.x;
    v[1] = di * a0.y + dii * s0.y + b0.y;
    v[2] = di * a0.z + dii * s0.z + b0.z;
    v[3] = di * a0.w + dii * s0.w + b0.w;
    v[4] = di * a1.x + dii * s1.x + b1.x;
    v[5] = di * a1.y + dii * s1.y + b1.y;
    v[6] = di * a1.z + dii * s1.z + b1.z;
    v[7] = di * a1.w + dii * s1.w + b1.w;
    size_t ob = (size_t)warp * ldc + c0;
    #pragma unroll
    for (int j = 0; j < 8; j += 2) {
        float v0 = v[j] > 0.f ? v[j] : SLOPE * v[j];
        float v1 = v[j+1] > 0.f ? v[j+1] : SLOPE * v[j+1];
        split_store(Oh, Ol, ob + j, v0, v1);
    }
}

// ---------------------------------------------------------------------------
// Final sigmoid head + small s_ci writeout
// ---------------------------------------------------------------------------
__global__ __launch_bounds__(256)
void final_kernel(const float* __restrict__ Wl2, const float* __restrict__ bl2, int n)
{
    int warp = (blockIdx.x * blockDim.x + threadIdx.x) >> 5;
    int lane = threadIdx.x & 31;
    if (warp >= n) return;
    const float* sr = g_S + (long)warp * EMB;
    float a = 0.f;
    #pragma unroll
    for (int j = 0; j < 8; j++) {
        int c = lane + 32 * j;
        a += sr[c] * Wl2[c];
    }
    #pragma unroll
    for (int off = 16; off > 0; off >>= 1)
        a += __shfl_xor_sync(0xffffffffu, a, off);
    if (lane == 0)
        g_sci[warp] = 1.f / (1.f + expf(-(a + bl2[0])));
}

__global__ void sci_writeout_kernel(float* __restrict__ out, int n)
{
    int i = blockIdx.x * blockDim.x + threadIdx.x;
    if (i < n) {
        float v = g_sci[i];
        out[i] = v;
        out[n + i] = v;
        out[2L * n + i] = v;
    }
}

// ---------------------------------------------------------------------------
// Launch: fork-join stream overlap (graph-capture legal).
// Side stream runs CSR prep + continuous embeds while the main stream runs
// weight/feature splits + the first two GEMMs. Join before agg1.
// ---------------------------------------------------------------------------
extern "C" void kernel_launch(void* const* d_in, const int* in_sizes, int n_in,
                              void* d_out, int out_size)
{
    const float* discrete_x = (const float*)d_in[0];
    const float* continous_x = (const float*)d_in[1];
    const float* Wd  = (const float*)d_in[2];
    const float* bd  = (const float*)d_in[3];
    const float* Wc1 = (const float*)d_in[4];
    const float* bc1 = (const float*)d_in[5];
    const float* Wc2 = (const float*)d_in[6];
    const float* bc2 = (const float*)d_in[7];
    const float* Wg0 = (const float*)d_in[8];
    const float* bg0 = (const float*)d_in[9];
    const float* Wg1 = (const float*)d_in[10];
    const float* bg1 = (const float*)d_in[11];
    const float* Wg2 = (const float*)d_in[12];
    const float* bg2 = (const float*)d_in[13];
    const float* Wf  = (const float*)d_in[14];
    const float* bf  = (const float*)d_in[15];
    const float* Wl1 = (const float*)d_in[16];
    const float* bl1 = (const float*)d_in[17];
    const float* Wl2 = (const float*)d_in[18];
    const float* bl2 = (const float*)d_in[19];
    const void*  edge_index = d_in[20];

    const int n = in_sizes[0] / DDISC;       // 50000
    const int e = in_sizes[20] / 2;          // 800000

    float *pY, *pS, *pB2;
    cudaGetSymbolAddress((void**)&pY, g_Y);
    cudaGetSymbolAddress((void**)&pS, g_S);
    cudaGetSymbolAddress((void**)&pB2, g_b2);
    __nv_bfloat16 *pAh, *pAl, *pGh, *pGl, *pHh, *pHl, *pDh, *pDl, *pWth, *pWtl;
    cudaGetSymbolAddress((void**)&pAh, g_Ah);
    cudaGetSymbolAddress((void**)&pAl, g_Al);
    cudaGetSymbolAddress((void**)&pGh, g_Gh);
    cudaGetSymbolAddress((void**)&pGl, g_Gl);
    cudaGetSymbolAddress((void**)&pHh, g_Hh);
    cudaGetSymbolAddress((void**)&pHl, g_Hl);
    cudaGetSymbolAddress((void**)&pDh, g_Dh);
    cudaGetSymbolAddress((void**)&pDl, g_Dl);
    cudaGetSymbolAddress((void**)&pWth, g_Wth);
    cudaGetSymbolAddress((void**)&pWtl, g_Wtl);

    cudaFuncSetAttribute(mma_gemm_kernel<0,0>, cudaFuncAttributeMaxDynamicSharedMemorySize, 2*STG);
    cudaFuncSetAttribute(mma_gemm_kernel<1,0>, cudaFuncAttributeMaxDynamicSharedMemorySize, 2*STG);
    cudaFuncSetAttribute(mma_gemm_kernel<1,2>, cudaFuncAttributeMaxDynamicSharedMemorySize, 2*STG);
    cudaFuncSetAttribute(mma_gemm_kernel<1,3>, cudaFuncAttributeMaxDynamicSharedMemorySize, 2*STG);

    dim3 blk(256);
    dim3 gblk(128);
    const int mtiles = (n + 127) / 128;   // 391
    float* outf = (float*)d_out;
    long tot = (long)n * HID;
    __nv_bfloat16* nb = nullptr;
    float* nf = nullptr;

    // ---- fork: side stream for CSR prep + continuous embeds ----
    cudaStream_t s1;
    cudaStreamCreateWithFlags(&s1, cudaStreamNonBlocking);
    cudaEvent_t eFork, eJoin;
    cudaEventCreateWithFlags(&eFork, cudaEventDisableTiming);
    cudaEventCreateWithFlags(&eJoin, cudaEventDisableTiming);
    cudaEventRecord(eFork, 0);
    cudaStreamWaitEvent(s1, eFork, 0);

    // side stream: edge CSR build + dinv + continuous embeds
    probe_kernel<<<1, 256, 0, s1>>>((const int*)edge_index, 2 * e);
    zero_cnt_kernel<<<(n + 255) / 256, blk, 0, s1>>>(n);
    count_kernel<<<(e + 255) / 256, blk, 0, s1>>>(edge_index, e, n);
    scan_kernel<<<1, 1024, 0, s1>>>(n);
    fill_kernel<<<(e + 255) / 256, blk, 0, s1>>>(edge_index, e, n);
    cont_embed_kernel<<<dim3(4, mtiles), blk, 0, s1>>>(continous_x, Wc1, bc1, Wc2, bc2,
                                                       pAh, pAl, n);

    // main stream: weight/feature splits + discrete GEMM + conv1 GEMM
    splitW_all_kernel<<<592, blk>>>(Wd, Wg0, Wg1, Wg2, Wf, Wl1, bd, bg0);
    {
        long nd = (long)n * DDISC;
        splitA_kernel<<<(unsigned)((nd + 255) / 256), blk>>>(discrete_x, pDh, pDl, nd);
    }
    mma_gemm_kernel<1,3><<<dim3(4, mtiles), gblk, 2*STG>>>(
        pDh, pDl, pWth + OW_DG, pWtl + OW_DG, pB2,
        nf, nf, 0, pAh, pAl, CAT, pGh, pGl, EMB, n, DDISC, 512);
    mma_gemm_kernel<0,0><<<dim3(2, mtiles), gblk, 2*STG>>>(
        pGh, pGl, pWth + OW_G1, pWtl + OW_G1, nf,
        pY, nf, EMB, nb, nb, 0, nb, nb, 0, n, EMB, EMB);

    // join: agg1 needs CSR (side) + conv1 GEMM (main)
    cudaEventRecord(eJoin, s1);
    cudaStreamWaitEvent(0, eJoin, 0);

    agg_kernel<<<(n * 32 + 255) / 256, blk>>>(pY, bg1, pGh, pGl, EMB, n);

    // ---- GCN conv 2 ----
    mma_gemm_kernel<0,0><<<dim3(2, mtiles), gblk, 2*STG>>>(
        pGh, pGl, pWth + OW_G2, pWtl + OW_G2, nf,
        pY, nf, EMB, nb, nb, 0, nb, nb, 0, n, EMB, EMB);
    agg_kernel<<<(n * 32 + 255) / 256, blk>>>(pY, bg2, pAh + 3*EMB, pAl + 3*EMB, CAT, n);

    // ---- fusion MLP: H -> split + dual fp32 into d_out ----
    mma_gemm_kernel<1,2><<<dim3(4, mtiles), gblk, 2*STG>>>(
        pAh, pAl, pWth + OW_F, pWtl + OW_F, bf,
        outf + 3L * n, outf + 3L * n + tot, HID, pHh, pHl, HID, nb, nb, 0, n, CAT, HID);
    mma_gemm_kernel<1,0><<<dim3(2, mtiles), gblk, 2*STG>>>(
        pHh, pHl, pWth + OW_L1, pWtl + OW_L1, bl1,
        pS, nf, EMB, nb, nb, 0, nb, nb, 0, n, HID, EMB);

    // ---- final sigmoid head + s_ci writeout ----
    final_kernel<<<(n * 32 + 255) / 256, blk>>>(Wl2, bl2, n);
    sci_writeout_kernel<<<(n + 255) / 256, blk>>>(outf, n);

    // NOTE: s1/eFork/eJoin are intentionally not destroyed here — destroying
    // a stream that participated in an ongoing capture before EndCapture can
    // invalidate the capture. These are host-side objects (no device memory);
    // kernel_launch is invoked only a handful of times (correctness + capture).
}

// round 12
// speedup vs baseline: 1.2069x; 1.0285x over previous
#include <cuda_runtime.h>
#include <cuda_bf16.h>
#include <math.h>
#include <stdint.h>

// ---------------------------------------------------------------------------
// Problem constants
// ---------------------------------------------------------------------------
#define NN    50000
#define EE    800000
#define EMB   256
#define HID   512
#define DDISC 64
#define DCONT 13
#define CAT   (4*EMB)      // 1024
#define SLOPE 0.01f

// transposed-weight pool offsets ([N,K] row-major, bf16)
#define OW_DG  0            // combined [512,64]: rows 0-255 Wd, 256-511 Wg0
#define OW_G1  32768        // [256,256]
#define OW_G2  98304        // [256,256]
#define OW_F   163840       // [512,1024]
#define OW_L1  688128       // [256,512]
#define OW_TOT 819200

// ---------------------------------------------------------------------------
// Scratch — __device__ globals (no cudaMalloc allowed)
// ---------------------------------------------------------------------------
__device__ float g_Y [(long)NN*EMB];     // conv pre-aggregation (fp32)
__device__ float g_S [(long)NN*EMB];     // s
__device__ float g_sci[NN];
__device__ float g_dinv[NN];
__device__ float g_b2[2*EMB];            // concat(bd, bg0)
__device__ int   g_cnt[NN];
__device__ int   g_rowptr[NN+1];
__device__ int   g_cursor[NN];
__device__ int   g_colsrc[EE];
__device__ int   g_blksum[64];
__device__ int   g_blkoff[64];
__device__ int   g_is64;

// bf16 split buffers (hi/lo)
__device__ __align__(16) __nv_bfloat16 g_Ah[(long)NN*CAT];   // concat split
__device__ __align__(16) __nv_bfloat16 g_Al[(long)NN*CAT];
__device__ __align__(16) __nv_bfloat16 g_Gh[(long)NN*EMB];   // gcn activation split
__device__ __align__(16) __nv_bfloat16 g_Gl[(long)NN*EMB];
__device__ __align__(16) __nv_bfloat16 g_Hh[(long)NN*HID];   // h_ci split
__device__ __align__(16) __nv_bfloat16 g_Hl[(long)NN*HID];
__device__ __align__(16) __nv_bfloat16 g_Dh[(long)NN*DDISC]; // discrete_x split
__device__ __align__(16) __nv_bfloat16 g_Dl[(long)NN*DDISC];
__device__ __align__(16) __nv_bfloat16 g_Wth[OW_TOT];        // transposed weight pool
__device__ __align__(16) __nv_bfloat16 g_Wtl[OW_TOT];

// ---------------------------------------------------------------------------
// asm helpers (base ISA only — must compile for compute_103)
// ---------------------------------------------------------------------------
__device__ __forceinline__ uint32_t smem_u32(const void* p) {
    uint32_t a;
    asm("{ .reg .u64 t; cvta.to.shared.u64 t, %1; cvt.u32.u64 %0, t; }" : "=r"(a) : "l"(p));
    return a;
}
__device__ __forceinline__ void ldsm4(uint32_t& r0, uint32_t& r1, uint32_t& r2, uint32_t& r3,
                                      uint32_t addr) {
    asm volatile("ldmatrix.sync.aligned.m8n8.x4.shared.b16 {%0,%1,%2,%3}, [%4];"
                 : "=r"(r0), "=r"(r1), "=r"(r2), "=r"(r3) : "r"(addr));
}
__device__ __forceinline__ void mma16816(float* c, const uint32_t* a, const uint32_t* b) {
    asm volatile(
        "mma.sync.aligned.m16n8k16.row.col.f32.bf16.bf16.f32 "
        "{%0,%1,%2,%3}, {%4,%5,%6,%7}, {%8,%9}, {%0,%1,%2,%3};"
        : "+f"(c[0]), "+f"(c[1]), "+f"(c[2]), "+f"(c[3])
        : "r"(a[0]), "r"(a[1]), "r"(a[2]), "r"(a[3]), "r"(b[0]), "r"(b[1]));
}
__device__ __forceinline__ void cp16(uint32_t dst, const void* src, int sz) {
    asm volatile("cp.async.cg.shared.global [%0], [%1], 16, %2;"
                 :: "r"(dst), "l"(src), "r"(sz) : "memory");
}
__device__ __forceinline__ void cp_commit() {
    asm volatile("cp.async.commit_group;" ::: "memory");
}
__device__ __forceinline__ void cp_wait1() {
    asm volatile("cp.async.wait_group 1;" ::: "memory");
}
__device__ __forceinline__ void cp_wait0() {
    asm volatile("cp.async.wait_group 0;" ::: "memory");
}
// byte offset inside a [rows][32 halfs] tile (row stride 64B, 16B-chunk swizzle)
__device__ __forceinline__ uint32_t swa(int r, int ci) {
    return (uint32_t)(r * 64 + ((ci ^ (r & 3) ^ ((r >> 2) & 1)) * 16));
}
__device__ __forceinline__ void split_store(__nv_bfloat16* H, __nv_bfloat16* L,
                                            size_t off, float v0, float v1) {
    __nv_bfloat16 h0 = __float2bfloat16(v0);
    __nv_bfloat16 h1 = __float2bfloat16(v1);
    __nv_bfloat16 l0 = __float2bfloat16(v0 - __bfloat162float(h0));
    __nv_bfloat16 l1 = __float2bfloat16(v1 - __bfloat162float(h1));
    *(__nv_bfloat162*)(H + off) = __nv_bfloat162(h0, h1);
    *(__nv_bfloat162*)(L + off) = __nv_bfloat162(l0, l1);
}

// ---------------------------------------------------------------------------
// bf16x3 HMMA GEMM, cp.async double-buffered, warp tile 64x64 (4 warps).
// CTA tile 128x128, 128 threads, K-chunk 32, K%32==0, N%128==0.
// MODE 0: write Cf fp32.
// MODE 2: write split (Ch,Cl) + fp32 into Cf AND Cf2.
// MODE 3: dual split dest — cols < 256 -> (Ch,Cl,lds); cols >= 256 -> (Ch2,Cl2,lds2).
// Dynamic smem: 2 stages x 32KB = 64KB.
// ---------------------------------------------------------------------------
#define STG 32768
template<int ACT, int MODE>
__global__ __launch_bounds__(128, 2)
void mma_gemm_kernel(const __nv_bfloat16* __restrict__ Ah,
                     const __nv_bfloat16* __restrict__ Al,
                     const __nv_bfloat16* __restrict__ Bh,   // [N,K]
                     const __nv_bfloat16* __restrict__ Bl,
                     const float* __restrict__ bias,
                     float* __restrict__ Cf, float* __restrict__ Cf2, int ldf,
                     __nv_bfloat16* __restrict__ Ch, __nv_bfloat16* __restrict__ Cl, int lds,
                     __nv_bfloat16* __restrict__ Ch2, __nv_bfloat16* __restrict__ Cl2, int lds2,
                     int M, int K, int N)
{
    extern __shared__ char sm[];
    const uint32_t sb = smem_u32(sm);
    const uint32_t oAH = 0, oAL = 8192, oBH = 16384, oBL = 24576;

    int tid = threadIdx.x;
    int wid = tid >> 5;
    int lane = tid & 31;
    int wm = wid & 1;              // 2 warp-rows of 64
    int wn = wid >> 1;             // 2 warp-cols of 64
    int row0 = blockIdx.y * 128;
    int col0 = blockIdx.x * 128;

    float acc[4][8][4];
    #pragma unroll
    for (int i = 0; i < 4; i++)
        #pragma unroll
        for (int j = 0; j < 8; j++)
            #pragma unroll
            for (int q = 0; q < 4; q++) acc[i][j][q] = 0.f;

    int Lg = lane >> 3;
    int Lr = lane & 7;
    const int nchunks = K >> 5;

    auto prefetch = [&](int ch, int stage) {
        int k0 = ch << 5;
        uint32_t base = sb + stage * STG;
        #pragma unroll
        for (int it = 0; it < 4; it++) {
            int idx = tid + it * 128;          // 0..511
            int r = idx >> 2, ci = idx & 3;
            uint32_t sw = swa(r, ci);
            int gr = row0 + r;
            int ok = (gr < M) ? 16 : 0;
            size_t ga = (size_t)(ok ? gr : 0) * K + k0 + ci * 8;
            cp16(base + oAH + sw, Ah + ga, ok);
            cp16(base + oAL + sw, Al + ga, ok);
            size_t gb = (size_t)(col0 + r) * K + k0 + ci * 8;
            cp16(base + oBH + sw, Bh + gb, 16);
            cp16(base + oBL + sw, Bl + gb, 16);
        }
        cp_commit();
    };

    prefetch(0, 0);
    for (int ch = 0; ch < nchunks; ch++) {
        if (ch + 1 < nchunks) {
            prefetch(ch + 1, (ch + 1) & 1);
            cp_wait1();
        } else {
            cp_wait0();
        }
        __syncthreads();
        uint32_t base = sb + (ch & 1) * STG;

        #pragma unroll
        for (int ks = 0; ks < 2; ks++) {
            uint32_t ah[4][4], al[4][4];
            #pragma unroll
            for (int ma = 0; ma < 4; ma++) {
                int ar = wm * 64 + ma * 16 + Lr + (Lg & 1) * 8;
                int ac = ks * 2 + (Lg >> 1);
                uint32_t sw = swa(ar, ac);
                ldsm4(ah[ma][0], ah[ma][1], ah[ma][2], ah[ma][3], base + oAH + sw);
                ldsm4(al[ma][0], al[ma][1], al[ma][2], al[ma][3], base + oAL + sw);
            }
            #pragma unroll
            for (int g = 0; g < 4; g++) {
                int br = wn * 64 + g * 16 + Lr + (Lg >> 1) * 8;
                int bc = ks * 2 + (Lg & 1);
                uint32_t sw = swa(br, bc);
                uint32_t bh[4], bl[4];
                ldsm4(bh[0], bh[1], bh[2], bh[3], base + oBH + sw);
                ldsm4(bl[0], bl[1], bl[2], bl[3], base + oBL + sw);
                #pragma unroll
                for (int ma = 0; ma < 4; ma++) {
                    mma16816(acc[ma][g*2+0], ah[ma], bh + 0);
                    mma16816(acc[ma][g*2+1], ah[ma], bh + 2);
                    mma16816(acc[ma][g*2+0], ah[ma], bl + 0);
                    mma16816(acc[ma][g*2+1], ah[ma], bl + 2);
                    mma16816(acc[ma][g*2+0], al[ma], bh + 0);
                    mma16816(acc[ma][g*2+1], al[ma], bh + 2);
                }
            }
        }
        __syncthreads();
    }

    // ---- epilogue ----
    int rbase = row0 + wm * 64 + (lane >> 2);
    int cbase = col0 + wn * 64 + (lane & 3) * 2;
    #pragma unroll
    for (int ma = 0; ma < 4; ma++) {
        #pragma unroll
        for (int na = 0; na < 8; na++) {
            int gc = cbase + na * 8;
            float b0 = bias ? bias[gc] : 0.f;
            float b1 = bias ? bias[gc + 1] : 0.f;
            #pragma unroll
            for (int h = 0; h < 2; h++) {
                int gr = rbase + ma * 16 + h * 8;
                if (gr < M) {
                    float v0 = acc[ma][na][h * 2 + 0] + b0;
                    float v1 = acc[ma][na][h * 2 + 1] + b1;
                    if (ACT == 1) {
                        v0 = v0 > 0.f ? v0 : SLOPE * v0;
                        v1 = v1 > 0.f ? v1 : SLOPE * v1;
                    }
                    if (MODE == 0 || MODE == 2) {
                        *(float2*)(Cf + (size_t)gr * ldf + gc) = make_float2(v0, v1);
                        if (MODE == 2)
                            *(float2*)(Cf2 + (size_t)gr * ldf + gc) = make_float2(v0, v1);
                    }
                    if (MODE == 2)
                        split_store(Ch, Cl, (size_t)gr * lds + gc, v0, v1);
                    if (MODE == 3) {
                        if (gc < 256)
                            split_store(Ch, Cl, (size_t)gr * lds + gc, v0, v1);
                        else
                            split_store(Ch2, Cl2, (size_t)gr * lds2 + (gc - 256), v0, v1);
                    }
                }
            }
        }
    }
}

// ---------------------------------------------------------------------------
// input feature split (fp32 -> bf16 hi/lo)
// ---------------------------------------------------------------------------
__global__ void splitA_kernel(const float* __restrict__ X,
                              __nv_bfloat16* __restrict__ H,
                              __nv_bfloat16* __restrict__ L, long n)
{
    long i = (long)blockIdx.x * blockDim.x + threadIdx.x;
    if (i >= n) return;
    float a = X[i];
    __nv_bfloat16 h = __float2bfloat16(a);
    H[i] = h;
    L[i] = __float2bfloat16(a - __bfloat162float(h));
}

// ---------------------------------------------------------------------------
// ONE kernel: transpose+split ALL weights into the pool, plus bias concat.
// ---------------------------------------------------------------------------
__global__ void splitW_all_kernel(const float* __restrict__ Wd,  const float* __restrict__ Wg0,
                                  const float* __restrict__ Wg1, const float* __restrict__ Wg2,
                                  const float* __restrict__ Wf,  const float* __restrict__ Wl1,
                                  const float* __restrict__ bd,  const float* __restrict__ bg0)
{
    const int c0 = DDISC*EMB;            // 16384
    const int c1 = c0 + DDISC*EMB;       // 32768
    const int c2 = c1 + EMB*EMB;         // 98304
    const int c3 = c2 + EMB*EMB;         // 163840
    const int c4 = c3 + CAT*HID;         // 688128
    const int c5 = c4 + HID*EMB;         // 819200
    for (long i = (long)blockIdx.x * blockDim.x + threadIdx.x;
         i < c5 + 2*EMB; i += (long)gridDim.x * blockDim.x) {
        if (i >= c5) {                   // bias concat tail
            int j = (int)(i - c5);
            g_b2[j] = (j < EMB) ? bd[j] : bg0[j - EMB];
            continue;
        }
        const float* W; long loc, off; int K, N;
        if (i < c0)      { W = Wd;  loc = i;      off = OW_DG;           K = DDISC; N = EMB; }
        else if (i < c1) { W = Wg0; loc = i - c0; off = OW_DG + (long)EMB*DDISC; K = DDISC; N = EMB; }
        else if (i < c2) { W = Wg1; loc = i - c1; off = OW_G1; K = EMB; N = EMB; }
        else if (i < c3) { W = Wg2; loc = i - c2; off = OW_G2; K = EMB; N = EMB; }
        else if (i < c4) { W = Wf;  loc = i - c3; off = OW_F;  K = CAT; N = HID; }
        else             { W = Wl1; loc = i - c4; off = OW_L1; K = HID; N = EMB; }
        int k = (int)(loc / N), nn = (int)(loc % N);
        float a = W[loc];
        __nv_bfloat16 h = __float2bfloat16(a);
        long o = off + (long)nn * K + k;
        g_Wth[o] = h;
        g_Wtl[o] = __float2bfloat16(a - __bfloat162float(h));
    }
}

// ---------------------------------------------------------------------------
// Edge dtype probe + graph preprocessing
// ---------------------------------------------------------------------------
__global__ void probe_kernel(const int* __restrict__ ei32, int nwords)
{
    __shared__ int nz;
    if (threadIdx.x == 0) nz = 0;
    __syncthreads();
    int lim = nwords < 4096 ? nwords : 4096;
    for (int i = 1 + 2 * threadIdx.x; i < lim; i += 2 * blockDim.x)
        if (ei32[i] != 0) atomicAdd(&nz, 1);
    __syncthreads();
    if (threadIdx.x == 0) g_is64 = (nz == 0) ? 1 : 0;
}

__device__ __forceinline__ int edge_at(const void* base, long i, int is64)
{
    return is64 ? (int)((const long long*)base)[i] : ((const int*)base)[i];
}

__global__ void zero_cnt_kernel(int n) {
    int i = blockIdx.x * blockDim.x + threadIdx.x;
    if (i < n) g_cnt[i] = 0;
}

__global__ void count_kernel(const void* __restrict__ ei, int e, int n) {
    int i = blockIdx.x * blockDim.x + threadIdx.x;
    if (i >= e) return;
    int is64 = g_is64;
    int d = edge_at(ei, (long)e + i, is64);
    if ((unsigned)d < (unsigned)n) atomicAdd(&g_cnt[d], 1);
}

// ---- 3-phase multi-block scan ----
// phase 1: per-block sum of 1024 counts + dinv
__global__ __launch_bounds__(1024)
void scan1_kernel(int n) {
    __shared__ int sh[1024];
    int i = blockIdx.x * 1024 + threadIdx.x;
    int v = (i < n) ? g_cnt[i] : 0;
    if (i < n) g_dinv[i] = rsqrtf((float)(v + 1));
    sh[threadIdx.x] = v;
    __syncthreads();
    #pragma unroll
    for (int off = 512; off > 0; off >>= 1) {
        if (threadIdx.x < off) sh[threadIdx.x] += sh[threadIdx.x + off];
        __syncthreads();
    }
    if (threadIdx.x == 0) g_blksum[blockIdx.x] = sh[0];
}

// phase 2: exclusive scan of <=64 block sums (single tiny block)
__global__ void scan2_kernel(int nblk) {
    __shared__ int sh[64];
    int t = threadIdx.x;
    int v = (t < nblk) ? g_blksum[t] : 0;
    sh[t] = v;
    __syncthreads();
    #pragma unroll
    for (int off = 1; off < 64; off <<= 1) {
        int u = (t >= off) ? sh[t - off] : 0;
        __syncthreads();
        sh[t] += u;
        __syncthreads();
    }
    if (t < nblk) g_blkoff[t] = sh[t] - v;
}

// phase 3: per-block inclusive scan + offset -> rowptr/cursor
__global__ __launch_bounds__(1024)
void scan3_kernel(int n, int nblk) {
    __shared__ int sh[1024];
    int i = blockIdx.x * 1024 + threadIdx.x;
    int v = (i < n) ? g_cnt[i] : 0;
    sh[threadIdx.x] = v;
    __syncthreads();
    #pragma unroll
    for (int off = 1; off < 1024; off <<= 1) {
        int u = (threadIdx.x >= off) ? sh[threadIdx.x - off] : 0;
        __syncthreads();
        sh[threadIdx.x] += u;
        __syncthreads();
    }
    int off0 = g_blkoff[blockIdx.x];
    if (i < n) {
        int ex = off0 + sh[threadIdx.x] - v;
        g_rowptr[i] = ex;
        g_cursor[i] = ex;
    }
    if (blockIdx.x == nblk - 1 && threadIdx.x == 1023)
        g_rowptr[n] = off0 + sh[1023];
}

__global__ void fill_kernel(const void* __restrict__ ei, int e, int n) {
    int i = blockIdx.x * blockDim.x + threadIdx.x;
    if (i >= e) return;
    int is64 = g_is64;
    int s = edge_at(ei, i, is64);
    int d = edge_at(ei, (long)e + i, is64);
    if ((unsigned)d < (unsigned)n && (unsigned)s < (unsigned)n) {
        int pos = atomicAdd(&g_cursor[d], 1);
        if (pos < EE) g_colsrc[pos] = s;
    }
}

// ---------------------------------------------------------------------------
// Merged continuous embeds (K=13), one launch: half = blockIdx.x>>1.
// ---------------------------------------------------------------------------
__global__ __launch_bounds__(256)
void cont_embed_kernel(const float* __restrict__ X,   // continous_x [M, 39]
                       const float* __restrict__ Wc1, const float* __restrict__ bc1,
                       const float* __restrict__ Wc2, const float* __restrict__ bc2,
                       __nv_bfloat16* __restrict__ Ch, __nv_bfloat16* __restrict__ Cl,
                       int M)
{
    const int K = DCONT, NC = EMB, lda = 3*DCONT;
    int half = blockIdx.x >> 1;
    int col0 = (blockIdx.x & 1) * 128;
    const float* A = X + half * DCONT;
    const float* W = half ? Wc2 : Wc1;
    const float* bias = half ? bc2 : bc1;
    __nv_bfloat16* OH = Ch + (1 + half) * EMB;
    __nv_bfloat16* OL = Cl + (1 + half) * EMB;

    __shared__ float As[16][128];
    __shared__ float Ws[16][128];

    int tid = threadIdx.x;
    int tx = tid & 15;
    int ty = tid >> 4;
    int row0 = blockIdx.y * 128;

    float acc[8][8];
    #pragma unroll
    for (int i = 0; i < 8; i++)
        #pragma unroll
        for (int j = 0; j < 8; j++) acc[i][j] = 0.f;

    {
        int a_row = tid >> 1;
        int a_col = (tid & 1) * 8;
        #pragma unroll
        for (int j = 0; j < 8; j++) {
            int r = row0 + a_row, c = a_col + j;
            As[a_col + j][a_row] = (r < M && c < K) ? A[(long)r * lda + c] : 0.f;
        }
        int w_k = tid >> 5;
        int w_n = (tid & 31) * 4;
        #pragma unroll
        for (int rep = 0; rep < 2; rep++) {
            int kk = w_k + rep * 8;
            #pragma unroll
            for (int j = 0; j < 4; j++) {
                int nn = col0 + w_n + j;
                Ws[kk][w_n + j] = (kk < K) ? W[(long)kk * NC + nn] : 0.f;
            }
        }
    }
    __syncthreads();
    #pragma unroll
    for (int k = 0; k < 13; k++) {
        float a[8], b[8];
        #pragma unroll
        for (int i = 0; i < 8; i++) a[i] = As[k][ty * 8 + i];
        #pragma unroll
        for (int j = 0; j < 8; j++) b[j] = Ws[k][tx * 8 + j];
        #pragma unroll
        for (int i = 0; i < 8; i++)
            #pragma unroll
            for (int j = 0; j < 8; j++)
                acc[i][j] += a[i] * b[j];
    }

    #pragma unroll
    for (int i = 0; i < 8; i++) {
        int r = row0 + ty * 8 + i;
        if (r >= M) continue;
        #pragma unroll
        for (int j = 0; j < 8; j += 2) {
            int c = col0 + tx * 8 + j;
            float v0 = acc[i][j] + bias[c];
            float v1 = acc[i][j + 1] + bias[c + 1];
            v0 = v0 > 0.f ? v0 : SLOPE * v0;
            v1 = v1 > 0.f ? v1 : SLOPE * v1;
            split_store(OH, OL, (size_t)r * CAT + c, v0, v1);
        }
    }
}

// ---------------------------------------------------------------------------
// GCN aggregation (one warp per node), float4 gathers, writes bf16 split.
// ---------------------------------------------------------------------------
__global__ __launch_bounds__(256)
void agg_kernel(const float* __restrict__ Y, const float* __restrict__ bias,
                __nv_bfloat16* __restrict__ Oh, __nv_bfloat16* __restrict__ Ol,
                int ldc, int n)
{
    int warp = (blockIdx.x * blockDim.x + threadIdx.x) >> 5;
    int lane = threadIdx.x & 31;
    if (warp >= n) return;
    int beg = g_rowptr[warp], end = g_rowptr[warp + 1];
    int c0 = lane * 8;
    float4 a0 = make_float4(0.f, 0.f, 0.f, 0.f);
    float4 a1 = make_float4(0.f, 0.f, 0.f, 0.f);
    for (int e = beg; e < end; e++) {
        int s = g_colsrc[e];
        float w = g_dinv[s];
        const float4* yr = (const float4*)(Y + (size_t)s * EMB + c0);
        float4 y0 = yr[0], y1 = yr[1];
        a0.x += y0.x * w; a0.y += y0.y * w; a0.z += y0.z * w; a0.w += y0.w * w;
        a1.x += y1.x * w; a1.y += y1.y * w; a1.z += y1.z * w; a1.w += y1.w * w;
    }
    float di = g_dinv[warp];
    float dii = di * di;
    const float4* ys = (const float4*)(Y + (size_t)warp * EMB + c0);
    float4 s0 = ys[0], s1 = ys[1];
    const float4* bp = (const float4*)(bias + c0);
    float4 b0 = bp[0], b1 = bp[1];
    float v[8];
    v[0] = di * a0.x + dii * s0.x + b0.x;
    v[1] = di * a0.y + dii * s0.y + b0.y;
    v[2] = di * a0.z + dii * s0.z + b0.z;
    v[3] = di * a0.w + dii * s0.w + b0.w;
    v[4] = di * a1.x + dii * s1.x + b1.x;
    v[5] = di * a1.y + dii * s1.y + b1.y;
    v[6] = di * a1.z + dii * s1.z + b1.z;
    v[7] = di * a1.w + dii * s1.w + b1.w;
    size_t ob = (size_t)warp * ldc + c0;
    #pragma unroll
    for (int j = 0; j < 8; j += 2) {
        float v0 = v[j] > 0.f ? v[j] : SLOPE * v[j];
        float v1 = v[j+1] > 0.f ? v[j+1] : SLOPE * v[j+1];
        split_store(Oh, Ol, ob + j, v0, v1);
    }
}

// ---------------------------------------------------------------------------
// Final sigmoid head + small s_ci writeout
// ---------------------------------------------------------------------------
__global__ __launch_bounds__(256)
void final_kernel(const float* __restrict__ Wl2, const float* __restrict__ bl2, int n)
{
    int warp = (blockIdx.x * blockDim.x + threadIdx.x) >> 5;
    int lane = threadIdx.x & 31;
    if (warp >= n) return;
    const float* sr = g_S + (long)warp * EMB;
    float a = 0.f;
    #pragma unroll
    for (int j = 0; j < 8; j++) {
        int c = lane + 32 * j;
        a += sr[c] * Wl2[c];
    }
    #pragma unroll
    for (int off = 16; off > 0; off >>= 1)
        a += __shfl_xor_sync(0xffffffffu, a, off);
    if (lane == 0)
        g_sci[warp] = 1.f / (1.f + expf(-(a + bl2[0])));
}

__global__ void sci_writeout_kernel(float* __restrict__ out, int n)
{
    int i = blockIdx.x * blockDim.x + threadIdx.x;
    if (i < n) {
        float v = g_sci[i];
        out[i] = v;
        out[n + i] = v;
        out[2L * n + i] = v;
    }
}

// ---------------------------------------------------------------------------
// Launch: fork-join stream overlap (graph-capture legal).
// ---------------------------------------------------------------------------
extern "C" void kernel_launch(void* const* d_in, const int* in_sizes, int n_in,
                              void* d_out, int out_size)
{
    const float* discrete_x = (const float*)d_in[0];
    const float* continous_x = (const float*)d_in[1];
    const float* Wd  = (const float*)d_in[2];
    const float* bd  = (const float*)d_in[3];
    const float* Wc1 = (const float*)d_in[4];
    const float* bc1 = (const float*)d_in[5];
    const float* Wc2 = (const float*)d_in[6];
    const float* bc2 = (const float*)d_in[7];
    const float* Wg0 = (const float*)d_in[8];
    const float* bg0 = (const float*)d_in[9];
    const float* Wg1 = (const float*)d_in[10];
    const float* bg1 = (const float*)d_in[11];
    const float* Wg2 = (const float*)d_in[12];
    const float* bg2 = (const float*)d_in[13];
    const float* Wf  = (const float*)d_in[14];
    const float* bf  = (const float*)d_in[15];
    const float* Wl1 = (const float*)d_in[16];
    const float* bl1 = (const float*)d_in[17];
    const float* Wl2 = (const float*)d_in[18];
    const float* bl2 = (const float*)d_in[19];
    const void*  edge_index = d_in[20];

    const int n = in_sizes[0] / DDISC;       // 50000
    const int e = in_sizes[20] / 2;          // 800000
    const int nblk = (n + 1023) / 1024;      // 49

    float *pY, *pS, *pB2;
    cudaGetSymbolAddress((void**)&pY, g_Y);
    cudaGetSymbolAddress((void**)&pS, g_S);
    cudaGetSymbolAddress((void**)&pB2, g_b2);
    __nv_bfloat16 *pAh, *pAl, *pGh, *pGl, *pHh, *pHl, *pDh, *pDl, *pWth, *pWtl;
    cudaGetSymbolAddress((void**)&pAh, g_Ah);
    cudaGetSymbolAddress((void**)&pAl, g_Al);
    cudaGetSymbolAddress((void**)&pGh, g_Gh);
    cudaGetSymbolAddress((void**)&pGl, g_Gl);
    cudaGetSymbolAddress((void**)&pHh, g_Hh);
    cudaGetSymbolAddress((void**)&pHl, g_Hl);
    cudaGetSymbolAddress((void**)&pDh, g_Dh);
    cudaGetSymbolAddress((void**)&pDl, g_Dl);
    cudaGetSymbolAddress((void**)&pWth, g_Wth);
    cudaGetSymbolAddress((void**)&pWtl, g_Wtl);

    cudaFuncSetAttribute(mma_gemm_kernel<0,0>, cudaFuncAttributeMaxDynamicSharedMemorySize, 2*STG);
    cudaFuncSetAttribute(mma_gemm_kernel<1,0>, cudaFuncAttributeMaxDynamicSharedMemorySize, 2*STG);
    cudaFuncSetAttribute(mma_gemm_kernel<1,2>, cudaFuncAttributeMaxDynamicSharedMemorySize, 2*STG);
    cudaFuncSetAttribute(mma_gemm_kernel<1,3>, cudaFuncAttributeMaxDynamicSharedMemorySize, 2*STG);

    dim3 blk(256);
    dim3 gblk(128);
    const int mtiles = (n + 127) / 128;   // 391
    float* outf = (float*)d_out;
    long tot = (long)n * HID;
    __nv_bfloat16* nb = nullptr;
    float* nf = nullptr;

    // ---- fork: side stream for CSR prep + continuous embeds ----
    cudaStream_t s1;
    cudaStreamCreateWithFlags(&s1, cudaStreamNonBlocking);
    cudaEvent_t eFork, eJoin;
    cudaEventCreateWithFlags(&eFork, cudaEventDisableTiming);
    cudaEventCreateWithFlags(&eJoin, cudaEventDisableTiming);
    cudaEventRecord(eFork, 0);
    cudaStreamWaitEvent(s1, eFork, 0);

    // side stream: edge CSR build + dinv + continuous embeds
    probe_kernel<<<1, 256, 0, s1>>>((const int*)edge_index, 2 * e);
    zero_cnt_kernel<<<(n + 255) / 256, blk, 0, s1>>>(n);
    count_kernel<<<(e + 255) / 256, blk, 0, s1>>>(edge_index, e, n);
    scan1_kernel<<<nblk, 1024, 0, s1>>>(n);
    scan2_kernel<<<1, 64, 0, s1>>>(nblk);
    scan3_kernel<<<nblk, 1024, 0, s1>>>(n, nblk);
    fill_kernel<<<(e + 255) / 256, blk, 0, s1>>>(edge_index, e, n);
    cont_embed_kernel<<<dim3(4, mtiles), blk, 0, s1>>>(continous_x, Wc1, bc1, Wc2, bc2,
                                                       pAh, pAl, n);

    // main stream: weight/feature splits + discrete GEMM + conv1 GEMM
    splitW_all_kernel<<<592, blk>>>(Wd, Wg0, Wg1, Wg2, Wf, Wl1, bd, bg0);
    {
        long nd = (long)n * DDISC;
        splitA_kernel<<<(unsigned)((nd + 255) / 256), blk>>>(discrete_x, pDh, pDl, nd);
    }
    mma_gemm_kernel<1,3><<<dim3(4, mtiles), gblk, 2*STG>>>(
        pDh, pDl, pWth + OW_DG, pWtl + OW_DG, pB2,
        nf, nf, 0, pAh, pAl, CAT, pGh, pGl, EMB, n, DDISC, 512);
    mma_gemm_kernel<0,0><<<dim3(2, mtiles), gblk, 2*STG>>>(
        pGh, pGl, pWth + OW_G1, pWtl + OW_G1, nf,
        pY, nf, EMB, nb, nb, 0, nb, nb, 0, n, EMB, EMB);

    // join: agg1 needs CSR (side) + conv1 GEMM (main)
    cudaEventRecord(eJoin, s1);
    cudaStreamWaitEvent(0, eJoin, 0);

    agg_kernel<<<(n * 32 + 255) / 256, blk>>>(pY, bg1, pGh, pGl, EMB, n);

    // ---- GCN conv 2 ----
    mma_gemm_kernel<0,0><<<dim3(2, mtiles), gblk, 2*STG>>>(
        pGh, pGl, pWth + OW_G2, pWtl + OW_G2, nf,
        pY, nf, EMB, nb, nb, 0, nb, nb, 0, n, EMB, EMB);
    agg_kernel<<<(n * 32 + 255) / 256, blk>>>(pY, bg2, pAh + 3*EMB, pAl + 3*EMB, CAT, n);

    // ---- fusion MLP: H -> split + dual fp32 into d_out ----
    mma_gemm_kernel<1,2><<<dim3(4, mtiles), gblk, 2*STG>>>(
        pAh, pAl, pWth + OW_F, pWtl + OW_F, bf,
        outf + 3L * n, outf + 3L * n + tot, HID, pHh, pHl, HID, nb, nb, 0, n, CAT, HID);
    mma_gemm_kernel<1,0><<<dim3(2, mtiles), gblk, 2*STG>>>(
        pHh, pHl, pWth + OW_L1, pWtl + OW_L1, bl1,
        pS, nf, EMB, nb, nb, 0, nb, nb, 0, n, HID, EMB);

    // ---- final sigmoid head + s_ci writeout ----
    final_kernel<<<(n * 32 + 255) / 256, blk>>>(Wl2, bl2, n);
    sci_writeout_kernel<<<(n + 255) / 256, blk>>>(outf, n);

    // NOTE: s1/eFork/eJoin intentionally not destroyed — destroying stream/
    // event objects that participated in an ongoing capture invalidates it.
    // Host-side objects only; no device memory involved.
}